// round 1
// baseline (speedup 1.0000x reference)
#include <cuda_runtime.h>
#include <math.h>

#define Mdim 8192
#define Hdim 768

// ---------------- scratch (static device globals; no allocation) ----------------
__device__ float g_hm[Mdim * Hdim];     // tanh(A W1m^T + b1m)
__device__ float g_hv[Mdim * Hdim];     // tanh(A W1v^T + b1v)
__device__ float g_mu[Mdim * Hdim];     // mu
__device__ float g_iv[Mdim * Hdim];     // exp(-tanh(...)) = inv_var
__device__ float g_colpart[2][64][Hdim];  // [0]=sum mu, [1]=sum mu^2 per 128-row chunk
__device__ float g_colmean[Hdim];
__device__ float g_colsq[Hdim];
__device__ float g_part[4096 * 2];      // per-block (pos_sum, pos-neg sum)

// ---------------- SGEMM: C[M,N] = epilogue(A[M,K] @ W[N,K]^T + bias) ------------
// Block tile 64x64, BK=16, 256 threads, 4x4 microtile.
// MODE 0: tanh(v)   MODE 1: v   MODE 2: exp(-tanh(v))
template <int MODE>
__global__ __launch_bounds__(256) void gemm_nt_epi(
    const float* __restrict__ A,     // [M, K] row-major, K contiguous
    const float* __restrict__ W,     // [N, K] row-major, K contiguous
    const float* __restrict__ bias,  // [N]
    float* __restrict__ C,           // [M, N]
    int M, int N, int K)
{
    __shared__ float As[16][68];  // [k][m], padded for aligned float4 reads
    __shared__ float Ws[16][68];  // [k][n]

    const int tid = threadIdx.x;
    const int tx = tid & 15;          // 0..15 -> n microtile
    const int ty = tid >> 4;          // 0..15 -> m microtile
    const int m0 = blockIdx.y * 64;
    const int n0 = blockIdx.x * 64;

    // load mapping: each thread loads one float4 of A and one of W per BK tile
    const int lrow = tid & 63;        // 0..63 row within tile
    const int lkq  = tid >> 6;        // 0..3  -> k offset lkq*4

    float acc[4][4];
#pragma unroll
    for (int i = 0; i < 4; i++)
#pragma unroll
        for (int j = 0; j < 4; j++) acc[i][j] = 0.0f;

    const float* Aptr = A + (size_t)(m0 + lrow) * K + lkq * 4;
    const float* Wptr = W + (size_t)(n0 + lrow) * K + lkq * 4;

    for (int kt = 0; kt < K; kt += 16) {
        float4 av = *(const float4*)(Aptr + kt);
        float4 wv = *(const float4*)(Wptr + kt);
        // transposed store: As[k][m] — conflict-free (lanes have distinct rows)
        As[lkq * 4 + 0][lrow] = av.x;
        As[lkq * 4 + 1][lrow] = av.y;
        As[lkq * 4 + 2][lrow] = av.z;
        As[lkq * 4 + 3][lrow] = av.w;
        Ws[lkq * 4 + 0][lrow] = wv.x;
        Ws[lkq * 4 + 1][lrow] = wv.y;
        Ws[lkq * 4 + 2][lrow] = wv.z;
        Ws[lkq * 4 + 3][lrow] = wv.w;
        __syncthreads();

#pragma unroll
        for (int k = 0; k < 16; k++) {
            float4 a4 = *(const float4*)&As[k][ty * 4];
            float4 w4 = *(const float4*)&Ws[k][tx * 4];
            float a[4] = {a4.x, a4.y, a4.z, a4.w};
            float w[4] = {w4.x, w4.y, w4.z, w4.w};
#pragma unroll
            for (int i = 0; i < 4; i++)
#pragma unroll
                for (int j = 0; j < 4; j++)
                    acc[i][j] = fmaf(a[i], w[j], acc[i][j]);
        }
        __syncthreads();
    }

    // epilogue + store (float4 per row)
    const int ncol = n0 + tx * 4;
    float4 b4 = *(const float4*)&bias[ncol];
    float bb[4] = {b4.x, b4.y, b4.z, b4.w};
#pragma unroll
    for (int i = 0; i < 4; i++) {
        int row = m0 + ty * 4 + i;
        float out[4];
#pragma unroll
        for (int j = 0; j < 4; j++) {
            float v = acc[i][j] + bb[j];
            if (MODE == 0)      out[j] = tanhf(v);
            else if (MODE == 1) out[j] = v;
            else                out[j] = expf(-tanhf(v));
        }
        *(float4*)&C[(size_t)row * N + ncol] =
            make_float4(out[0], out[1], out[2], out[3]);
    }
}

// ------------- column moments of mu: stage 1 (partial over 128-row chunks) ------
__global__ __launch_bounds__(256) void col_moments_s1() {
    const int col = blockIdx.x * 256 + threadIdx.x;   // gridDim.x = 3
    const int rc = blockIdx.y;                        // 64 row chunks of 128
    float s = 0.0f, s2 = 0.0f;
    const int r0 = rc * 128;
#pragma unroll 4
    for (int r = 0; r < 128; r++) {
        float v = g_mu[(size_t)(r0 + r) * Hdim + col];
        s += v;
        s2 = fmaf(v, v, s2);
    }
    g_colpart[0][rc][col] = s;
    g_colpart[1][rc][col] = s2;
}

// ------------- column moments: stage 2 (deterministic final sum) ----------------
__global__ __launch_bounds__(256) void col_moments_s2() {
    const int col = blockIdx.x * 256 + threadIdx.x;   // gridDim.x = 3
    float s = 0.0f, s2 = 0.0f;
    for (int rc = 0; rc < 64; rc++) {
        s += g_colpart[0][rc][col];
        s2 += g_colpart[1][rc][col];
    }
    const float invB = 1.0f / (float)Mdim;
    g_colmean[col] = s * invB;
    g_colsq[col] = s2 * invB;
}

// ------------- final elementwise + per-block partial reduction ------------------
__global__ __launch_bounds__(256) void final_elem(const float* __restrict__ modal_b) {
    __shared__ float shp[256];
    __shared__ float shd[256];
    const int tid = threadIdx.x;
    const size_t total = (size_t)Mdim * Hdim;           // 6,291,456
    const size_t stride = (size_t)gridDim.x * 256;      // 1,048,576
    size_t idx = (size_t)blockIdx.x * 256 + tid;

    float sp = 0.0f, sd = 0.0f;
    for (; idx < total; idx += stride) {
        int col = (int)(idx % Hdim);
        float mu = g_mu[idx];
        float iv = g_iv[idx];
        float mb = modal_b[idx];
        float dmb = mu - mb;
        float pos = -dmb * dmb * 0.5f * iv;
        float pair = g_colsq[col] - 2.0f * mu * g_colmean[col] + mu * mu;
        float neg = -pair * 0.5f * iv;
        sp += pos;
        sd += (pos - neg);
    }
    shp[tid] = sp;
    shd[tid] = sd;
    __syncthreads();
    for (int s = 128; s > 0; s >>= 1) {
        if (tid < s) {
            shp[tid] += shp[tid + s];
            shd[tid] += shd[tid + s];
        }
        __syncthreads();
    }
    if (tid == 0) {
        g_part[blockIdx.x * 2 + 0] = shp[0];
        g_part[blockIdx.x * 2 + 1] = shd[0];
    }
}

// ------------- final deterministic scalar reduction ------------------------------
__global__ __launch_bounds__(256) void final_reduce(float* __restrict__ out, int nblocks) {
    __shared__ float shp[256];
    __shared__ float shd[256];
    const int tid = threadIdx.x;
    float sp = 0.0f, sd = 0.0f;
    for (int i = tid; i < nblocks; i += 256) {
        sp += g_part[i * 2 + 0];
        sd += g_part[i * 2 + 1];
    }
    shp[tid] = sp;
    shd[tid] = sd;
    __syncthreads();
    for (int s = 128; s > 0; s >>= 1) {
        if (tid < s) {
            shp[tid] += shp[tid + s];
            shd[tid] += shd[tid + s];
        }
        __syncthreads();
    }
    if (tid == 0) {
        const float invB = 1.0f / (float)Mdim;
        out[0] = shp[0] * invB;   // lld  = mean(pos_sum)
        out[1] = shd[0] * invB;   // bound = mean(pos_sum - neg_sum)
    }
}

// --------------------------------- launcher --------------------------------------
extern "C" void kernel_launch(void* const* d_in, const int* in_sizes, int n_in,
                              void* d_out, int out_size) {
    const float* modal_a = (const float*)d_in[0];
    const float* modal_b = (const float*)d_in[1];
    const float* W1m = (const float*)d_in[2];
    const float* b1m = (const float*)d_in[3];
    const float* W2m = (const float*)d_in[4];
    const float* b2m = (const float*)d_in[5];
    const float* W1v = (const float*)d_in[6];
    const float* b1v = (const float*)d_in[7];
    const float* W2v = (const float*)d_in[8];
    const float* b2v = (const float*)d_in[9];
    float* out = (float*)d_out;

    float *hm, *hv, *mu, *iv;
    cudaGetSymbolAddress((void**)&hm, g_hm);
    cudaGetSymbolAddress((void**)&hv, g_hv);
    cudaGetSymbolAddress((void**)&mu, g_mu);
    cudaGetSymbolAddress((void**)&iv, g_iv);

    dim3 gblk(256);
    dim3 ggrid(Hdim / 64, Mdim / 64);   // (12, 128)

    // layer 1 (both branches): tanh epilogue
    gemm_nt_epi<0><<<ggrid, gblk>>>(modal_a, W1m, b1m, hm, Mdim, Hdim, Hdim);
    gemm_nt_epi<0><<<ggrid, gblk>>>(modal_a, W1v, b1v, hv, Mdim, Hdim, Hdim);
    // layer 2: mu (identity), inv_var (exp(-tanh))
    gemm_nt_epi<1><<<ggrid, gblk>>>(hm, W2m, b2m, mu, Mdim, Hdim, Hdim);
    gemm_nt_epi<2><<<ggrid, gblk>>>(hv, W2v, b2v, iv, Mdim, Hdim, Hdim);

    // per-feature batch moments of mu (deterministic two-stage)
    col_moments_s1<<<dim3(3, 64), 256>>>();
    col_moments_s2<<<dim3(3), 256>>>();

    // final fused elementwise + reduction
    final_elem<<<4096, 256>>>(modal_b);
    final_reduce<<<1, 256>>>(out, 4096);
}

// round 3
// speedup vs baseline: 4.0887x; 4.0887x over previous
#include <cuda_runtime.h>
#include <cstdint>
#include <math.h>

#define Mdim 8192
#define Hdim 768
#define BM 128
#define BN 128
#define BK 32
#define RS 36          // padded smem row stride (floats): banks (4g+tg) conflict-free
#define NKT (Hdim / BK) // 24

// ---------------- scratch (static device globals; no allocation) ----------------
__device__ float g_at[Mdim * Hdim];    // tf32-rounded modal_a
__device__ float g_w[4][Hdim * Hdim];  // tf32-rounded W1m, W1v, W2m, W2v
__device__ float g_hm[Mdim * Hdim];    // tanh(layer1m), tf32-rounded
__device__ float g_hv[Mdim * Hdim];    // tanh(layer1v), tf32-rounded
__device__ float g_mu[Mdim * Hdim];
__device__ float g_iv[Mdim * Hdim];
__device__ float g_colpart[2][64][Hdim];
__device__ float g_colmean[Hdim];
__device__ float g_colsq[Hdim];
__device__ float g_part[4096 * 2];

// ---------------------------- helpers -------------------------------------------
__device__ __forceinline__ uint32_t smem_u32(const void* p) {
    uint32_t a;
    asm("{ .reg .u64 t; cvta.to.shared.u64 t, %1; cvt.u32.u64 %0, t; }"
        : "=r"(a) : "l"(p));
    return a;
}
__device__ __forceinline__ uint32_t tf32_rna(float x) {
    uint32_t r;
    asm("cvt.rna.tf32.f32 %0, %1;" : "=r"(r) : "f"(x));
    return r;
}

// -------------------- pack: fp32 -> tf32-rounded fp32 (same layout) -------------
__global__ __launch_bounds__(256) void pack_tf32(const float* __restrict__ src,
                                                 float* __restrict__ dst, int n4) {
    int i = blockIdx.x * 256 + threadIdx.x;
    for (; i < n4; i += gridDim.x * 256) {
        float4 v = ((const float4*)src)[i];
        v.x = __uint_as_float(tf32_rna(v.x));
        v.y = __uint_as_float(tf32_rna(v.y));
        v.z = __uint_as_float(tf32_rna(v.z));
        v.w = __uint_as_float(tf32_rna(v.w));
        ((float4*)dst)[i] = v;
    }
}

// ------------------------------- tf32 mma.sync GEMM -----------------------------
// C[M, 768] = epi(A[M,768] @ W[768,768]^T + bias), A/W tf32-rounded fp32.
// MODE 0: tanh -> tf32 round    MODE 1: identity    MODE 2: exp(-tanh)
template <int MODE>
__global__ __launch_bounds__(256) void gemm_mma(
    const float* __restrict__ A, const float* __restrict__ Bw,
    const float* __restrict__ bias, float* __restrict__ C)
{
    extern __shared__ float sm[];
    float* As = sm;                    // [2][BM][RS]
    float* Bs = sm + 2 * BM * RS;      // [2][BN][RS]

    const int tid = threadIdx.x;
    const int wid = tid >> 5, lane = tid & 31;
    const int g = lane >> 2, tg = lane & 3;
    const int wm0 = (wid & 3) * 32;    // warp M offset (4 warps along M)
    const int wn0 = (wid >> 2) * 64;   // warp N offset (2 warps along N)
    const int m0 = blockIdx.y * BM;
    const int n0 = blockIdx.x * BN;

    const int lrow = tid >> 3;         // 0..31
    const int lkq = (tid & 7) * 4;     // 0,4,...,28

    const uint32_t sA = smem_u32(As);
    const uint32_t sB = smem_u32(Bs);

    float c[2][8][4];
#pragma unroll
    for (int t = 0; t < 2; t++)
#pragma unroll
        for (int j = 0; j < 8; j++)
#pragma unroll
            for (int q = 0; q < 4; q++) c[t][j][q] = 0.0f;

    const float* agb = A + (size_t)(m0 + lrow) * Hdim + lkq;
    const float* bgb = Bw + (size_t)(n0 + lrow) * Hdim + lkq;
    const uint32_t dab = sA + (uint32_t)(lrow * RS + lkq) * 4;
    const uint32_t dbb = sB + (uint32_t)(lrow * RS + lkq) * 4;

#define PREFETCH(kt, buf) do { \
    const float* _ag = agb + (kt) * BK; \
    const float* _bg = bgb + (kt) * BK; \
    uint32_t _da = dab + (buf) * BM * RS * 4; \
    uint32_t _db = dbb + (buf) * BN * RS * 4; \
    _Pragma("unroll") \
    for (int r = 0; r < 4; r++) { \
        asm volatile("cp.async.cg.shared.global [%0], [%1], 16;" \
            :: "r"(_da + r * 32 * RS * 4), "l"(_ag + (size_t)r * 32 * Hdim) : "memory"); \
        asm volatile("cp.async.cg.shared.global [%0], [%1], 16;" \
            :: "r"(_db + r * 32 * RS * 4), "l"(_bg + (size_t)r * 32 * Hdim) : "memory"); \
    } \
    asm volatile("cp.async.commit_group;" ::: "memory"); \
} while (0)

    PREFETCH(0, 0);

    for (int kt = 0; kt < NKT; kt++) {
        if (kt + 1 < NKT) {
            PREFETCH(kt + 1, (kt + 1) & 1);
            asm volatile("cp.async.wait_group 1;" ::: "memory");
        } else {
            asm volatile("cp.async.wait_group 0;" ::: "memory");
        }
        __syncthreads();

        const float* Ab = As + (kt & 1) * BM * RS;
        const float* Bb = Bs + (kt & 1) * BN * RS;
#pragma unroll
        for (int ks = 0; ks < 4; ks++) {
            const int col = ks * 8 + tg;
            uint32_t a[2][4];
#pragma unroll
            for (int t = 0; t < 2; t++) {
                const int rb = wm0 + t * 16 + g;
                a[t][0] = __float_as_uint(Ab[rb * RS + col]);
                a[t][1] = __float_as_uint(Ab[(rb + 8) * RS + col]);
                a[t][2] = __float_as_uint(Ab[rb * RS + col + 4]);
                a[t][3] = __float_as_uint(Ab[(rb + 8) * RS + col + 4]);
            }
#pragma unroll
            for (int j = 0; j < 8; j++) {
                const int nr = wn0 + j * 8 + g;
                uint32_t b0 = __float_as_uint(Bb[nr * RS + col]);
                uint32_t b1 = __float_as_uint(Bb[nr * RS + col + 4]);
#pragma unroll
                for (int t = 0; t < 2; t++) {
                    asm volatile(
                        "mma.sync.aligned.m16n8k8.row.col.f32.tf32.tf32.f32 "
                        "{%0,%1,%2,%3}, {%4,%5,%6,%7}, {%8,%9}, {%0,%1,%2,%3};"
                        : "+f"(c[t][j][0]), "+f"(c[t][j][1]),
                          "+f"(c[t][j][2]), "+f"(c[t][j][3])
                        : "r"(a[t][0]), "r"(a[t][1]), "r"(a[t][2]), "r"(a[t][3]),
                          "r"(b0), "r"(b1));
                }
            }
        }
        __syncthreads();
    }
#undef PREFETCH

    // epilogue
#pragma unroll
    for (int j = 0; j < 8; j++) {
        const int ncol = n0 + wn0 + j * 8 + tg * 2;
        const float bv0 = bias[ncol];
        const float bv1 = bias[ncol + 1];
#pragma unroll
        for (int t = 0; t < 2; t++) {
#pragma unroll
            for (int h = 0; h < 2; h++) {
                const int row = m0 + wm0 + t * 16 + g + h * 8;
                float v0 = c[t][j][h * 2 + 0] + bv0;
                float v1 = c[t][j][h * 2 + 1] + bv1;
                if (MODE == 0) {
                    v0 = __uint_as_float(tf32_rna(tanhf(v0)));
                    v1 = __uint_as_float(tf32_rna(tanhf(v1)));
                } else if (MODE == 2) {
                    v0 = expf(-tanhf(v0));
                    v1 = expf(-tanhf(v1));
                }
                *(float2*)&C[(size_t)row * Hdim + ncol] = make_float2(v0, v1);
            }
        }
    }
}

// ------------- column moments of mu (deterministic two-stage) -------------------
__global__ __launch_bounds__(256) void col_moments_s1() {
    const int col = blockIdx.x * 256 + threadIdx.x;
    const int rc = blockIdx.y;
    float s = 0.0f, s2 = 0.0f;
    const int r0 = rc * 128;
#pragma unroll 4
    for (int r = 0; r < 128; r++) {
        float v = g_mu[(size_t)(r0 + r) * Hdim + col];
        s += v;
        s2 = fmaf(v, v, s2);
    }
    g_colpart[0][rc][col] = s;
    g_colpart[1][rc][col] = s2;
}

__global__ __launch_bounds__(256) void col_moments_s2() {
    const int col = blockIdx.x * 256 + threadIdx.x;
    float s = 0.0f, s2 = 0.0f;
    for (int rc = 0; rc < 64; rc++) {
        s += g_colpart[0][rc][col];
        s2 += g_colpart[1][rc][col];
    }
    const float invB = 1.0f / (float)Mdim;
    g_colmean[col] = s * invB;
    g_colsq[col] = s2 * invB;
}

__global__ __launch_bounds__(256) void final_elem(const float* __restrict__ modal_b) {
    __shared__ float shp[256];
    __shared__ float shd[256];
    const int tid = threadIdx.x;
    const size_t total = (size_t)Mdim * Hdim;
    const size_t stride = (size_t)gridDim.x * 256;
    size_t idx = (size_t)blockIdx.x * 256 + tid;

    float sp = 0.0f, sd = 0.0f;
    for (; idx < total; idx += stride) {
        int col = (int)(idx % Hdim);
        float mu = g_mu[idx];
        float iv = g_iv[idx];
        float mb = modal_b[idx];
        float dmb = mu - mb;
        float pos = -dmb * dmb * 0.5f * iv;
        float pair = g_colsq[col] - 2.0f * mu * g_colmean[col] + mu * mu;
        float neg = -pair * 0.5f * iv;
        sp += pos;
        sd += (pos - neg);
    }
    shp[tid] = sp;
    shd[tid] = sd;
    __syncthreads();
    for (int s = 128; s > 0; s >>= 1) {
        if (tid < s) { shp[tid] += shp[tid + s]; shd[tid] += shd[tid + s]; }
        __syncthreads();
    }
    if (tid == 0) {
        g_part[blockIdx.x * 2 + 0] = shp[0];
        g_part[blockIdx.x * 2 + 1] = shd[0];
    }
}

__global__ __launch_bounds__(256) void final_reduce(float* __restrict__ out, int nblocks) {
    __shared__ float shp[256];
    __shared__ float shd[256];
    const int tid = threadIdx.x;
    float sp = 0.0f, sd = 0.0f;
    for (int i = tid; i < nblocks; i += 256) {
        sp += g_part[i * 2 + 0];
        sd += g_part[i * 2 + 1];
    }
    shp[tid] = sp;
    shd[tid] = sd;
    __syncthreads();
    for (int s = 128; s > 0; s >>= 1) {
        if (tid < s) { shp[tid] += shp[tid + s]; shd[tid] += shd[tid + s]; }
        __syncthreads();
    }
    if (tid == 0) {
        const float invB = 1.0f / (float)Mdim;
        out[0] = shp[0] * invB;
        out[1] = shd[0] * invB;
    }
}

// --------------------------------- launcher --------------------------------------
extern "C" void kernel_launch(void* const* d_in, const int* in_sizes, int n_in,
                              void* d_out, int out_size) {
    const float* modal_a = (const float*)d_in[0];
    const float* modal_b = (const float*)d_in[1];
    const float* Wsrc[4] = {(const float*)d_in[2], (const float*)d_in[6],
                            (const float*)d_in[4], (const float*)d_in[8]};
    const float* b1m = (const float*)d_in[3];
    const float* b2m = (const float*)d_in[5];
    const float* b1v = (const float*)d_in[7];
    const float* b2v = (const float*)d_in[9];
    float* out = (float*)d_out;

    float *at, *w, *hm, *hv, *mu, *iv;
    cudaGetSymbolAddress((void**)&at, g_at);
    cudaGetSymbolAddress((void**)&w, g_w);
    cudaGetSymbolAddress((void**)&hm, g_hm);
    cudaGetSymbolAddress((void**)&hv, g_hv);
    cudaGetSymbolAddress((void**)&mu, g_mu);
    cudaGetSymbolAddress((void**)&iv, g_iv);
    float* w1m = w + 0 * (size_t)Hdim * Hdim;
    float* w1v = w + 1 * (size_t)Hdim * Hdim;
    float* w2m = w + 2 * (size_t)Hdim * Hdim;
    float* w2v = w + 3 * (size_t)Hdim * Hdim;

    const int SMEM_BYTES = 2 * (BM + BN) * RS * 4;  // 73728
    cudaFuncSetAttribute(gemm_mma<0>, cudaFuncAttributeMaxDynamicSharedMemorySize, SMEM_BYTES);
    cudaFuncSetAttribute(gemm_mma<1>, cudaFuncAttributeMaxDynamicSharedMemorySize, SMEM_BYTES);
    cudaFuncSetAttribute(gemm_mma<2>, cudaFuncAttributeMaxDynamicSharedMemorySize, SMEM_BYTES);

    // tf32-round inputs (RNA), layout unchanged
    pack_tf32<<<1024, 256>>>(modal_a, at, Mdim * Hdim / 4);
    pack_tf32<<<288, 256>>>(Wsrc[0], w1m, Hdim * Hdim / 4);
    pack_tf32<<<288, 256>>>(Wsrc[1], w1v, Hdim * Hdim / 4);
    pack_tf32<<<288, 256>>>(Wsrc[2], w2m, Hdim * Hdim / 4);
    pack_tf32<<<288, 256>>>(Wsrc[3], w2v, Hdim * Hdim / 4);

    dim3 ggrid(Hdim / BN, Mdim / BM);   // (6, 64) = 384 CTAs
    gemm_mma<0><<<ggrid, 256, SMEM_BYTES>>>(at, w1m, b1m, hm);
    gemm_mma<0><<<ggrid, 256, SMEM_BYTES>>>(at, w1v, b1v, hv);
    gemm_mma<1><<<ggrid, 256, SMEM_BYTES>>>(hm, w2m, b2m, mu);
    gemm_mma<2><<<ggrid, 256, SMEM_BYTES>>>(hv, w2v, b2v, iv);

    col_moments_s1<<<dim3(3, 64), 256>>>();
    col_moments_s2<<<dim3(3), 256>>>();
    final_elem<<<4096, 256>>>(modal_b);
    final_reduce<<<1, 256>>>(out, 4096);
}

// round 4
// speedup vs baseline: 5.8481x; 1.4303x over previous
#include <cuda_runtime.h>
#include <cuda_fp16.h>
#include <cstdint>
#include <math.h>

#define Mdim 8192
#define Hdim 768
#define BM 128
#define BN 128
#define BK 32
#define RSW 20          // smem row stride in 32-bit words (40 halves): banks 4g+tg
#define NKT (Hdim / BK) // 24

// ---------------- scratch (static device globals; no allocation) ----------------
__device__ __half g_ah[Mdim * Hdim];     // fp16 modal_a
__device__ __half g_wh[4][Hdim * Hdim];  // fp16 W1m, W1v, W2m, W2v
__device__ __half g_hm[Mdim * Hdim];     // fp16 tanh(layer1m)
__device__ __half g_hv[Mdim * Hdim];     // fp16 tanh(layer1v)
__device__ float g_mu[Mdim * Hdim];
__device__ float g_iv[Mdim * Hdim];
__device__ float g_colpart[2][64][Hdim];
__device__ float g_colmean[Hdim];
__device__ float g_colsq[Hdim];
__device__ float g_part[4096 * 2];

// ---------------------------- helpers -------------------------------------------
__device__ __forceinline__ uint32_t smem_u32(const void* p) {
    uint32_t a;
    asm("{ .reg .u64 t; cvta.to.shared.u64 t, %1; cvt.u32.u64 %0, t; }"
        : "=r"(a) : "l"(p));
    return a;
}

// -------------------- pack: fp32 -> fp16 ----------------------------------------
__global__ __launch_bounds__(256) void pack_h(const float* __restrict__ src,
                                              __half* __restrict__ dst, int n4) {
    int i = blockIdx.x * 256 + threadIdx.x;
    for (; i < n4; i += gridDim.x * 256) {
        float4 v = ((const float4*)src)[i];
        __half2 h0 = __floats2half2_rn(v.x, v.y);
        __half2 h1 = __floats2half2_rn(v.z, v.w);
        *(uint2*)(dst + (size_t)i * 4) =
            make_uint2(*(uint32_t*)&h0, *(uint32_t*)&h1);
    }
}

// ------------------------------- fp16 mma.sync GEMM -----------------------------
// C[M, 768] = epi(A[M,768] @ W[768,768]^T + bias), fp16 in, fp32 accum.
// MODE 0: tanh -> half store (Ch)   MODE 1: identity -> fp32 (Cp)
// MODE 2: exp(-tanh) -> fp32 (Cp)
template <int MODE>
__global__ __launch_bounds__(256) void gemm_mma(
    const __half* __restrict__ A, const __half* __restrict__ Bw,
    const float* __restrict__ bias, float* __restrict__ Cp,
    __half* __restrict__ Ch)
{
    __shared__ uint32_t As[2 * BM * RSW];   // [2][128][20] words
    __shared__ uint32_t Bs[2 * BN * RSW];

    const int tid = threadIdx.x;
    const int wid = tid >> 5, lane = tid & 31;
    const int g = lane >> 2, tg = lane & 3;
    const int wm0 = (wid & 3) * 32;    // 4 warps along M
    const int wn0 = (wid >> 2) * 64;   // 2 warps along N
    const int m0 = blockIdx.y * BM;
    const int n0 = blockIdx.x * BN;

    const uint32_t sA = smem_u32(As);
    const uint32_t sB = smem_u32(Bs);

    // loader mapping: 256 threads, 2 rows each (r, r+64), 16B chunk (tid&3)
    const int lrow = tid >> 2;          // 0..63
    const int lc = tid & 3;             // 0..3  -> halves lc*8

    float c[2][8][4];
#pragma unroll
    for (int t = 0; t < 2; t++)
#pragma unroll
        for (int j = 0; j < 8; j++)
#pragma unroll
            for (int q = 0; q < 4; q++) c[t][j][q] = 0.0f;

    const __half* agb = A + (size_t)(m0 + lrow) * Hdim + lc * 8;
    const __half* bgb = Bw + (size_t)(n0 + lrow) * Hdim + lc * 8;
    const uint32_t dab = sA + (uint32_t)(lrow * RSW + lc * 4) * 4;
    const uint32_t dbb = sB + (uint32_t)(lrow * RSW + lc * 4) * 4;
    const uint32_t rowstep = 64 * RSW * 4;     // +64 rows in bytes
    const uint32_t bufstep = BM * RSW * 4;     // buffer stride in bytes

#define PREFETCH(kt, buf) do { \
    const __half* _ag = agb + (kt) * BK; \
    const __half* _bg = bgb + (kt) * BK; \
    uint32_t _da = dab + (buf) * bufstep; \
    uint32_t _db = dbb + (buf) * bufstep; \
    asm volatile("cp.async.cg.shared.global [%0], [%1], 16;" \
        :: "r"(_da), "l"(_ag) : "memory"); \
    asm volatile("cp.async.cg.shared.global [%0], [%1], 16;" \
        :: "r"(_da + rowstep), "l"(_ag + (size_t)64 * Hdim) : "memory"); \
    asm volatile("cp.async.cg.shared.global [%0], [%1], 16;" \
        :: "r"(_db), "l"(_bg) : "memory"); \
    asm volatile("cp.async.cg.shared.global [%0], [%1], 16;" \
        :: "r"(_db + rowstep), "l"(_bg + (size_t)64 * Hdim) : "memory"); \
    asm volatile("cp.async.commit_group;" ::: "memory"); \
} while (0)

    PREFETCH(0, 0);

    for (int kt = 0; kt < NKT; kt++) {
        if (kt + 1 < NKT) {
            PREFETCH(kt + 1, (kt + 1) & 1);
            asm volatile("cp.async.wait_group 1;" ::: "memory");
        } else {
            asm volatile("cp.async.wait_group 0;" ::: "memory");
        }
        __syncthreads();

        const uint32_t* Ab = As + (kt & 1) * BM * RSW;
        const uint32_t* Bb = Bs + (kt & 1) * BN * RSW;
#pragma unroll
        for (int ks = 0; ks < 2; ks++) {        // two k16 steps per BK=32
            const int kw = ks * 8 + tg;         // word col within row
            uint32_t a[2][4];
#pragma unroll
            for (int t = 0; t < 2; t++) {
                const int rb = wm0 + t * 16 + g;
                a[t][0] = Ab[rb * RSW + kw];
                a[t][1] = Ab[(rb + 8) * RSW + kw];
                a[t][2] = Ab[rb * RSW + kw + 4];
                a[t][3] = Ab[(rb + 8) * RSW + kw + 4];
            }
#pragma unroll
            for (int j = 0; j < 8; j++) {
                const int nr = wn0 + j * 8 + g;
                uint32_t b0 = Bb[nr * RSW + kw];
                uint32_t b1 = Bb[nr * RSW + kw + 4];
#pragma unroll
                for (int t = 0; t < 2; t++) {
                    asm volatile(
                        "mma.sync.aligned.m16n8k16.row.col.f32.f16.f16.f32 "
                        "{%0,%1,%2,%3}, {%4,%5,%6,%7}, {%8,%9}, {%0,%1,%2,%3};"
                        : "+f"(c[t][j][0]), "+f"(c[t][j][1]),
                          "+f"(c[t][j][2]), "+f"(c[t][j][3])
                        : "r"(a[t][0]), "r"(a[t][1]), "r"(a[t][2]), "r"(a[t][3]),
                          "r"(b0), "r"(b1));
                }
            }
        }
        __syncthreads();
    }
#undef PREFETCH

    // epilogue: D fragment (g, 2tg/2tg+1) rows g,g+8 per 16-row tile
#pragma unroll
    for (int j = 0; j < 8; j++) {
        const int ncol = n0 + wn0 + j * 8 + tg * 2;
        const float bv0 = bias[ncol];
        const float bv1 = bias[ncol + 1];
#pragma unroll
        for (int t = 0; t < 2; t++) {
#pragma unroll
            for (int h = 0; h < 2; h++) {
                const int row = m0 + wm0 + t * 16 + g + h * 8;
                float v0 = c[t][j][h * 2 + 0] + bv0;
                float v1 = c[t][j][h * 2 + 1] + bv1;
                if (MODE == 0) {
                    __half2 hv = __floats2half2_rn(tanhf(v0), tanhf(v1));
                    *(__half2*)&Ch[(size_t)row * Hdim + ncol] = hv;
                } else {
                    if (MODE == 2) {
                        v0 = expf(-tanhf(v0));
                        v1 = expf(-tanhf(v1));
                    }
                    *(float2*)&Cp[(size_t)row * Hdim + ncol] = make_float2(v0, v1);
                }
            }
        }
    }
}

// ------------- column moments of mu (deterministic two-stage) -------------------
__global__ __launch_bounds__(256) void col_moments_s1() {
    const int col = blockIdx.x * 256 + threadIdx.x;
    const int rc = blockIdx.y;
    float s = 0.0f, s2 = 0.0f;
    const int r0 = rc * 128;
#pragma unroll 4
    for (int r = 0; r < 128; r++) {
        float v = g_mu[(size_t)(r0 + r) * Hdim + col];
        s += v;
        s2 = fmaf(v, v, s2);
    }
    g_colpart[0][rc][col] = s;
    g_colpart[1][rc][col] = s2;
}

__global__ __launch_bounds__(256) void col_moments_s2() {
    const int col = blockIdx.x * 256 + threadIdx.x;
    float s = 0.0f, s2 = 0.0f;
    for (int rc = 0; rc < 64; rc++) {
        s += g_colpart[0][rc][col];
        s2 += g_colpart[1][rc][col];
    }
    const float invB = 1.0f / (float)Mdim;
    g_colmean[col] = s * invB;
    g_colsq[col] = s2 * invB;
}

__global__ __launch_bounds__(256) void final_elem(const float* __restrict__ modal_b) {
    __shared__ float shp[256];
    __shared__ float shd[256];
    const int tid = threadIdx.x;
    const size_t total = (size_t)Mdim * Hdim;
    const size_t stride = (size_t)gridDim.x * 256;
    size_t idx = (size_t)blockIdx.x * 256 + tid;

    float sp = 0.0f, sd = 0.0f;
    for (; idx < total; idx += stride) {
        int col = (int)(idx % Hdim);
        float mu = g_mu[idx];
        float iv = g_iv[idx];
        float mb = modal_b[idx];
        float dmb = mu - mb;
        float pos = -dmb * dmb * 0.5f * iv;
        float pair = g_colsq[col] - 2.0f * mu * g_colmean[col] + mu * mu;
        float neg = -pair * 0.5f * iv;
        sp += pos;
        sd += (pos - neg);
    }
    shp[tid] = sp;
    shd[tid] = sd;
    __syncthreads();
    for (int s = 128; s > 0; s >>= 1) {
        if (tid < s) { shp[tid] += shp[tid + s]; shd[tid] += shd[tid + s]; }
        __syncthreads();
    }
    if (tid == 0) {
        g_part[blockIdx.x * 2 + 0] = shp[0];
        g_part[blockIdx.x * 2 + 1] = shd[0];
    }
}

__global__ __launch_bounds__(256) void final_reduce(float* __restrict__ out, int nblocks) {
    __shared__ float shp[256];
    __shared__ float shd[256];
    const int tid = threadIdx.x;
    float sp = 0.0f, sd = 0.0f;
    for (int i = tid; i < nblocks; i += 256) {
        sp += g_part[i * 2 + 0];
        sd += g_part[i * 2 + 1];
    }
    shp[tid] = sp;
    shd[tid] = sd;
    __syncthreads();
    for (int s = 128; s > 0; s >>= 1) {
        if (tid < s) { shp[tid] += shp[tid + s]; shd[tid] += shd[tid + s]; }
        __syncthreads();
    }
    if (tid == 0) {
        const float invB = 1.0f / (float)Mdim;
        out[0] = shp[0] * invB;
        out[1] = shd[0] * invB;
    }
}

// --------------------------------- launcher --------------------------------------
extern "C" void kernel_launch(void* const* d_in, const int* in_sizes, int n_in,
                              void* d_out, int out_size) {
    const float* modal_a = (const float*)d_in[0];
    const float* modal_b = (const float*)d_in[1];
    const float* Wsrc[4] = {(const float*)d_in[2], (const float*)d_in[6],
                            (const float*)d_in[4], (const float*)d_in[8]};
    const float* b1m = (const float*)d_in[3];
    const float* b2m = (const float*)d_in[5];
    const float* b1v = (const float*)d_in[7];
    const float* b2v = (const float*)d_in[9];
    float* out = (float*)d_out;

    __half *ah, *wh, *hm, *hv;
    float *mu, *iv;
    cudaGetSymbolAddress((void**)&ah, g_ah);
    cudaGetSymbolAddress((void**)&wh, g_wh);
    cudaGetSymbolAddress((void**)&hm, g_hm);
    cudaGetSymbolAddress((void**)&hv, g_hv);
    cudaGetSymbolAddress((void**)&mu, g_mu);
    cudaGetSymbolAddress((void**)&iv, g_iv);
    __half* w1m = wh + 0 * (size_t)Hdim * Hdim;
    __half* w1v = wh + 1 * (size_t)Hdim * Hdim;
    __half* w2m = wh + 2 * (size_t)Hdim * Hdim;
    __half* w2v = wh + 3 * (size_t)Hdim * Hdim;

    // fp32 -> fp16 packs
    pack_h<<<1024, 256>>>(modal_a, ah, Mdim * Hdim / 4);
    pack_h<<<288, 256>>>(Wsrc[0], w1m, Hdim * Hdim / 4);
    pack_h<<<288, 256>>>(Wsrc[1], w1v, Hdim * Hdim / 4);
    pack_h<<<288, 256>>>(Wsrc[2], w2m, Hdim * Hdim / 4);
    pack_h<<<288, 256>>>(Wsrc[3], w2v, Hdim * Hdim / 4);

    dim3 ggrid(Hdim / BN, Mdim / BM);   // (6, 64) = 384 CTAs
    gemm_mma<0><<<ggrid, 256>>>(ah, w1m, b1m, nullptr, hm);
    gemm_mma<0><<<ggrid, 256>>>(ah, w1v, b1v, nullptr, hv);
    gemm_mma<1><<<ggrid, 256>>>(hm, w2m, b2m, mu, nullptr);
    gemm_mma<2><<<ggrid, 256>>>(hv, w2v, b2v, iv, nullptr);

    col_moments_s1<<<dim3(3, 64), 256>>>();
    col_moments_s2<<<dim3(3), 256>>>();
    final_elem<<<4096, 256>>>(modal_b);
    final_reduce<<<1, 256>>>(out, 4096);
}

// round 5
// speedup vs baseline: 5.9994x; 1.0259x over previous
#include <cuda_runtime.h>
#include <cuda_fp16.h>
#include <cstdint>
#include <math.h>

#define Mdim 8192
#define Hdim 768
#define BM 128
#define BN 128
#define BK 32
#define RSW 20          // smem row stride in 32-bit words (40 halves): banks 4g+tg
#define NKT (Hdim / BK) // 24
#define PSTAGES 4       // cp.async pipeline depth

// ---------------- scratch (static device globals; no allocation) ----------------
__device__ __half g_ah[Mdim * Hdim];     // fp16 modal_a
__device__ __half g_wh[4][Hdim * Hdim];  // fp16 W1m, W1v, W2m, W2v
__device__ __half g_hm[Mdim * Hdim];     // fp16 tanh(layer1m)
__device__ __half g_hv[Mdim * Hdim];     // fp16 tanh(layer1v)
__device__ float g_mu[Mdim * Hdim];
__device__ float g_iv[Mdim * Hdim];
__device__ float g_colpart[2][64][Hdim];
__device__ float g_colmean[Hdim];
__device__ float g_colsq[Hdim];
__device__ float g_part[4096 * 2];

// ---------------------------- helpers -------------------------------------------
__device__ __forceinline__ uint32_t smem_u32(const void* p) {
    uint32_t a;
    asm("{ .reg .u64 t; cvta.to.shared.u64 t, %1; cvt.u32.u64 %0, t; }"
        : "=r"(a) : "l"(p));
    return a;
}

// -------------------- pack: fp32 -> fp16 (modal_a) ------------------------------
__global__ __launch_bounds__(256) void pack_h(const float* __restrict__ src,
                                              __half* __restrict__ dst, int n4) {
    int i = blockIdx.x * 256 + threadIdx.x;
    for (; i < n4; i += gridDim.x * 256) {
        float4 v = ((const float4*)src)[i];
        __half2 h0 = __floats2half2_rn(v.x, v.y);
        __half2 h1 = __floats2half2_rn(v.z, v.w);
        *(uint2*)(dst + (size_t)i * 4) =
            make_uint2(*(uint32_t*)&h0, *(uint32_t*)&h1);
    }
}

// -------------------- pack all 4 weights in one launch ---------------------------
__global__ __launch_bounds__(256) void pack_w4(
    const float* __restrict__ w0, const float* __restrict__ w1,
    const float* __restrict__ w2, const float* __restrict__ w3,
    __half* __restrict__ dst) {
    const int n4 = Hdim * Hdim / 4;
    const float* src = (blockIdx.y == 0) ? w0 : (blockIdx.y == 1) ? w1
                        : (blockIdx.y == 2) ? w2 : w3;
    __half* d = dst + (size_t)blockIdx.y * Hdim * Hdim;
    int i = blockIdx.x * 256 + threadIdx.x;
    for (; i < n4; i += gridDim.x * 256) {
        float4 v = ((const float4*)src)[i];
        __half2 h0 = __floats2half2_rn(v.x, v.y);
        __half2 h1 = __floats2half2_rn(v.z, v.w);
        *(uint2*)(d + (size_t)i * 4) =
            make_uint2(*(uint32_t*)&h0, *(uint32_t*)&h1);
    }
}

// ------------------------------- fp16 mma.sync GEMM -----------------------------
// C[M, 768] = epi(A[M,768] @ W[768,768]^T + bias), fp16 in, fp32 accum.
// MODE 0: tanh -> half store (Ch)   MODE 1: identity -> fp32 (Cp)
// MODE 2: exp(-tanh) -> fp32 (Cp)
template <int MODE>
__global__ __launch_bounds__(256) void gemm_mma(
    const __half* __restrict__ A, const __half* __restrict__ Bw,
    const float* __restrict__ bias, float* __restrict__ Cp,
    __half* __restrict__ Ch)
{
    extern __shared__ uint32_t sm[];
    uint32_t* As = sm;                          // [PSTAGES][BM][RSW]
    uint32_t* Bs = sm + PSTAGES * BM * RSW;     // [PSTAGES][BN][RSW]

    const int tid = threadIdx.x;
    const int wid = tid >> 5, lane = tid & 31;
    const int g = lane >> 2, tg = lane & 3;
    const int wm0 = (wid & 3) * 32;    // 4 warps along M
    const int wn0 = (wid >> 2) * 64;   // 2 warps along N
    const int m0 = blockIdx.y * BM;
    const int n0 = blockIdx.x * BN;

    const uint32_t sA = smem_u32(As);
    const uint32_t sB = smem_u32(Bs);

    // loader mapping: 256 threads, 2 rows each (r, r+64), 16B chunk (tid&3)
    const int lrow = tid >> 2;          // 0..63
    const int lc = tid & 3;             // 0..3  -> halves lc*8

    float c[2][8][4];
#pragma unroll
    for (int t = 0; t < 2; t++)
#pragma unroll
        for (int j = 0; j < 8; j++)
#pragma unroll
            for (int q = 0; q < 4; q++) c[t][j][q] = 0.0f;

    const __half* agb = A + (size_t)(m0 + lrow) * Hdim + lc * 8;
    const __half* bgb = Bw + (size_t)(n0 + lrow) * Hdim + lc * 8;
    const uint32_t dab = sA + (uint32_t)(lrow * RSW + lc * 4) * 4;
    const uint32_t dbb = sB + (uint32_t)(lrow * RSW + lc * 4) * 4;
    const uint32_t rowstep = 64 * RSW * 4;     // +64 rows in bytes
    const uint32_t bufstep = BM * RSW * 4;     // stage stride in bytes

#define PREFETCH(kt) do { \
    const __half* _ag = agb + (kt) * BK; \
    const __half* _bg = bgb + (kt) * BK; \
    uint32_t _da = dab + ((kt) % PSTAGES) * bufstep; \
    uint32_t _db = dbb + ((kt) % PSTAGES) * bufstep; \
    asm volatile("cp.async.cg.shared.global [%0], [%1], 16;" \
        :: "r"(_da), "l"(_ag) : "memory"); \
    asm volatile("cp.async.cg.shared.global [%0], [%1], 16;" \
        :: "r"(_da + rowstep), "l"(_ag + (size_t)64 * Hdim) : "memory"); \
    asm volatile("cp.async.cg.shared.global [%0], [%1], 16;" \
        :: "r"(_db), "l"(_bg) : "memory"); \
    asm volatile("cp.async.cg.shared.global [%0], [%1], 16;" \
        :: "r"(_db + rowstep), "l"(_bg + (size_t)64 * Hdim) : "memory"); \
    asm volatile("cp.async.commit_group;" ::: "memory"); \
} while (0)

    PREFETCH(0);
    PREFETCH(1);
    PREFETCH(2);

    for (int kt = 0; kt < NKT; kt++) {
        // 3 groups pending at entry; wait until oldest (kt) lands.
        asm volatile("cp.async.wait_group 2;" ::: "memory");
        __syncthreads();

        // refill: buffer (kt+3)%4 == (kt-1)%4, fully consumed by all warps
        // (they passed the barrier above after finishing kt-1's compute).
        if (kt + 3 < NKT) PREFETCH(kt + 3);

        const uint32_t* Ab = As + (kt % PSTAGES) * BM * RSW;
        const uint32_t* Bb = Bs + (kt % PSTAGES) * BN * RSW;
#pragma unroll
        for (int ks = 0; ks < 2; ks++) {        // two k16 steps per BK=32
            const int kw = ks * 8 + tg;         // word col within row
            uint32_t a[2][4];
#pragma unroll
            for (int t = 0; t < 2; t++) {
                const int rb = wm0 + t * 16 + g;
                a[t][0] = Ab[rb * RSW + kw];
                a[t][1] = Ab[(rb + 8) * RSW + kw];
                a[t][2] = Ab[rb * RSW + kw + 4];
                a[t][3] = Ab[(rb + 8) * RSW + kw + 4];
            }
#pragma unroll
            for (int j = 0; j < 8; j++) {
                const int nr = wn0 + j * 8 + g;
                uint32_t b0 = Bb[nr * RSW + kw];
                uint32_t b1 = Bb[nr * RSW + kw + 4];
#pragma unroll
                for (int t = 0; t < 2; t++) {
                    asm volatile(
                        "mma.sync.aligned.m16n8k16.row.col.f32.f16.f16.f32 "
                        "{%0,%1,%2,%3}, {%4,%5,%6,%7}, {%8,%9}, {%0,%1,%2,%3};"
                        : "+f"(c[t][j][0]), "+f"(c[t][j][1]),
                          "+f"(c[t][j][2]), "+f"(c[t][j][3])
                        : "r"(a[t][0]), "r"(a[t][1]), "r"(a[t][2]), "r"(a[t][3]),
                          "r"(b0), "r"(b1));
                }
            }
        }
        __syncthreads();
    }
#undef PREFETCH

    // epilogue: D fragment (g, 2tg/2tg+1) rows g,g+8 per 16-row tile
#pragma unroll
    for (int j = 0; j < 8; j++) {
        const int ncol = n0 + wn0 + j * 8 + tg * 2;
        const float bv0 = bias[ncol];
        const float bv1 = bias[ncol + 1];
#pragma unroll
        for (int t = 0; t < 2; t++) {
#pragma unroll
            for (int h = 0; h < 2; h++) {
                const int row = m0 + wm0 + t * 16 + g + h * 8;
                float v0 = c[t][j][h * 2 + 0] + bv0;
                float v1 = c[t][j][h * 2 + 1] + bv1;
                if (MODE == 0) {
                    __half2 hv = __floats2half2_rn(tanhf(v0), tanhf(v1));
                    *(__half2*)&Ch[(size_t)row * Hdim + ncol] = hv;
                } else {
                    if (MODE == 2) {
                        v0 = expf(-tanhf(v0));
                        v1 = expf(-tanhf(v1));
                    }
                    *(float2*)&Cp[(size_t)row * Hdim + ncol] = make_float2(v0, v1);
                }
            }
        }
    }
}

// ------------- column moments of mu (deterministic two-stage) -------------------
__global__ __launch_bounds__(256) void col_moments_s1() {
    const int col = blockIdx.x * 256 + threadIdx.x;
    const int rc = blockIdx.y;
    float s = 0.0f, s2 = 0.0f;
    const int r0 = rc * 128;
#pragma unroll 4
    for (int r = 0; r < 128; r++) {
        float v = g_mu[(size_t)(r0 + r) * Hdim + col];
        s += v;
        s2 = fmaf(v, v, s2);
    }
    g_colpart[0][rc][col] = s;
    g_colpart[1][rc][col] = s2;
}

__global__ __launch_bounds__(256) void col_moments_s2() {
    const int col = blockIdx.x * 256 + threadIdx.x;
    float s = 0.0f, s2 = 0.0f;
    for (int rc = 0; rc < 64; rc++) {
        s += g_colpart[0][rc][col];
        s2 += g_colpart[1][rc][col];
    }
    const float invB = 1.0f / (float)Mdim;
    g_colmean[col] = s * invB;
    g_colsq[col] = s2 * invB;
}

__global__ __launch_bounds__(256) void final_elem(const float* __restrict__ modal_b) {
    __shared__ float shp[256];
    __shared__ float shd[256];
    const int tid = threadIdx.x;
    const size_t total = (size_t)Mdim * Hdim;
    const size_t stride = (size_t)gridDim.x * 256;
    size_t idx = (size_t)blockIdx.x * 256 + tid;

    float sp = 0.0f, sd = 0.0f;
    for (; idx < total; idx += stride) {
        int col = (int)(idx % Hdim);
        float mu = g_mu[idx];
        float iv = g_iv[idx];
        float mb = modal_b[idx];
        float dmb = mu - mb;
        float pos = -dmb * dmb * 0.5f * iv;
        float pair = g_colsq[col] - 2.0f * mu * g_colmean[col] + mu * mu;
        float neg = -pair * 0.5f * iv;
        sp += pos;
        sd += (pos - neg);
    }
    shp[tid] = sp;
    shd[tid] = sd;
    __syncthreads();
    for (int s = 128; s > 0; s >>= 1) {
        if (tid < s) { shp[tid] += shp[tid + s]; shd[tid] += shd[tid + s]; }
        __syncthreads();
    }
    if (tid == 0) {
        g_part[blockIdx.x * 2 + 0] = shp[0];
        g_part[blockIdx.x * 2 + 1] = shd[0];
    }
}

__global__ __launch_bounds__(256) void final_reduce(float* __restrict__ out, int nblocks) {
    __shared__ float shp[256];
    __shared__ float shd[256];
    const int tid = threadIdx.x;
    float sp = 0.0f, sd = 0.0f;
    for (int i = tid; i < nblocks; i += 256) {
        sp += g_part[i * 2 + 0];
        sd += g_part[i * 2 + 1];
    }
    shp[tid] = sp;
    shd[tid] = sd;
    __syncthreads();
    for (int s = 128; s > 0; s >>= 1) {
        if (tid < s) { shp[tid] += shp[tid + s]; shd[tid] += shd[tid + s]; }
        __syncthreads();
    }
    if (tid == 0) {
        const float invB = 1.0f / (float)Mdim;
        out[0] = shp[0] * invB;
        out[1] = shd[0] * invB;
    }
}

// --------------------------------- launcher --------------------------------------
extern "C" void kernel_launch(void* const* d_in, const int* in_sizes, int n_in,
                              void* d_out, int out_size) {
    const float* modal_a = (const float*)d_in[0];
    const float* modal_b = (const float*)d_in[1];
    const float* b1m = (const float*)d_in[3];
    const float* b2m = (const float*)d_in[5];
    const float* b1v = (const float*)d_in[7];
    const float* b2v = (const float*)d_in[9];
    float* out = (float*)d_out;

    __half *ah, *wh, *hm, *hv;
    float *mu, *iv;
    cudaGetSymbolAddress((void**)&ah, g_ah);
    cudaGetSymbolAddress((void**)&wh, g_wh);
    cudaGetSymbolAddress((void**)&hm, g_hm);
    cudaGetSymbolAddress((void**)&hv, g_hv);
    cudaGetSymbolAddress((void**)&mu, g_mu);
    cudaGetSymbolAddress((void**)&iv, g_iv);
    __half* w1m = wh + 0 * (size_t)Hdim * Hdim;
    __half* w1v = wh + 1 * (size_t)Hdim * Hdim;
    __half* w2m = wh + 2 * (size_t)Hdim * Hdim;
    __half* w2v = wh + 3 * (size_t)Hdim * Hdim;

    const int SMEM_BYTES = PSTAGES * (BM + BN) * RSW * 4;  // 81920
    cudaFuncSetAttribute(gemm_mma<0>, cudaFuncAttributeMaxDynamicSharedMemorySize, SMEM_BYTES);
    cudaFuncSetAttribute(gemm_mma<1>, cudaFuncAttributeMaxDynamicSharedMemorySize, SMEM_BYTES);
    cudaFuncSetAttribute(gemm_mma<2>, cudaFuncAttributeMaxDynamicSharedMemorySize, SMEM_BYTES);

    // fp32 -> fp16 packs (modal_a + all four weights in one launch)
    pack_h<<<1024, 256>>>(modal_a, ah, Mdim * Hdim / 4);
    pack_w4<<<dim3(72, 4), 256>>>((const float*)d_in[2], (const float*)d_in[6],
                                  (const float*)d_in[4], (const float*)d_in[8], wh);

    dim3 ggrid(Hdim / BN, Mdim / BM);   // (6, 64) = 384 CTAs
    gemm_mma<0><<<ggrid, 256, SMEM_BYTES>>>(ah, w1m, b1m, nullptr, hm);
    gemm_mma<0><<<ggrid, 256, SMEM_BYTES>>>(ah, w1v, b1v, nullptr, hv);
    gemm_mma<1><<<ggrid, 256, SMEM_BYTES>>>(hm, w2m, b2m, mu, nullptr);
    gemm_mma<2><<<ggrid, 256, SMEM_BYTES>>>(hv, w2v, b2v, iv, nullptr);

    col_moments_s1<<<dim3(3, 64), 256>>>();
    col_moments_s2<<<dim3(3), 256>>>();
    final_elem<<<4096, 256>>>(modal_b);
    final_reduce<<<1, 256>>>(out, 4096);
}

// round 6
// speedup vs baseline: 6.8154x; 1.1360x over previous
#include <cuda_runtime.h>
#include <cuda_fp16.h>
#include <cstdint>
#include <math.h>

#define Mdim 8192
#define Hdim 768
#define BM 128
#define BN 128
#define BK 32
#define RSW 20          // smem row stride in 32-bit words (40 halves)
#define NKT (Hdim / BK) // 24
#define PSTAGES 4       // cp.async pipeline depth

// ---------------- scratch (static device globals; no allocation) ----------------
__device__ __half g_ah[Mdim * Hdim];     // fp16 modal_a
__device__ __half g_wh[4][Hdim * Hdim];  // fp16 W1m, W1v, W2m, W2v
__device__ __half g_hm[Mdim * Hdim];     // fp16 tanh(layer1m)
__device__ __half g_hv[Mdim * Hdim];     // fp16 tanh(layer1v)
__device__ float g_mu[Mdim * Hdim];
__device__ float g_iv[Mdim * Hdim];
__device__ float g_colpart[2][64][Hdim];
__device__ float g_colmean[Hdim];
__device__ float g_colsq[Hdim];
__device__ float g_part[4096 * 2];

// ---------------------------- helpers -------------------------------------------
__device__ __forceinline__ uint32_t smem_u32(const void* p) {
    uint32_t a;
    asm("{ .reg .u64 t; cvta.to.shared.u64 t, %1; cvt.u32.u64 %0, t; }"
        : "=r"(a) : "l"(p));
    return a;
}
#define LDSM_X4(r0, r1, r2, r3, addr) \
    asm volatile("ldmatrix.sync.aligned.m8n8.x4.shared.b16 {%0,%1,%2,%3}, [%4];" \
        : "=r"(r0), "=r"(r1), "=r"(r2), "=r"(r3) : "r"(addr))

// -------------------- pack: fp32 -> fp16 (modal_a) ------------------------------
__global__ __launch_bounds__(256) void pack_h(const float* __restrict__ src,
                                              __half* __restrict__ dst, int n4) {
    int i = blockIdx.x * 256 + threadIdx.x;
    for (; i < n4; i += gridDim.x * 256) {
        float4 v = ((const float4*)src)[i];
        __half2 h0 = __floats2half2_rn(v.x, v.y);
        __half2 h1 = __floats2half2_rn(v.z, v.w);
        *(uint2*)(dst + (size_t)i * 4) =
            make_uint2(*(uint32_t*)&h0, *(uint32_t*)&h1);
    }
}

// -------------------- pack all 4 weights in one launch ---------------------------
__global__ __launch_bounds__(256) void pack_w4(
    const float* __restrict__ w0, const float* __restrict__ w1,
    const float* __restrict__ w2, const float* __restrict__ w3,
    __half* __restrict__ dst) {
    const int n4 = Hdim * Hdim / 4;
    const float* src = (blockIdx.y == 0) ? w0 : (blockIdx.y == 1) ? w1
                        : (blockIdx.y == 2) ? w2 : w3;
    __half* d = dst + (size_t)blockIdx.y * Hdim * Hdim;
    int i = blockIdx.x * 256 + threadIdx.x;
    for (; i < n4; i += gridDim.x * 256) {
        float4 v = ((const float4*)src)[i];
        __half2 h0 = __floats2half2_rn(v.x, v.y);
        __half2 h1 = __floats2half2_rn(v.z, v.w);
        *(uint2*)(d + (size_t)i * 4) =
            make_uint2(*(uint32_t*)&h0, *(uint32_t*)&h1);
    }
}

// -------------------- fused dual-branch fp16 mma.sync GEMM ----------------------
// blockIdx.z = 0: C0 = epi<M0>(A0 @ W0^T + bias0)
// blockIdx.z = 1: C1 = epi<M1>(A1 @ W1^T + bias1)
// MODE 0: tanh -> half store    MODE 1: identity -> fp32    MODE 2: exp(-tanh) -> fp32
template <int M0, int M1>
__global__ __launch_bounds__(256) void gemm_fused(
    const __half* __restrict__ A0, const __half* __restrict__ A1,
    const __half* __restrict__ W0, const __half* __restrict__ W1,
    const float* __restrict__ bias0, const float* __restrict__ bias1,
    float* __restrict__ P0, float* __restrict__ P1,
    __half* __restrict__ H0, __half* __restrict__ H1)
{
    extern __shared__ uint32_t sm[];
    uint32_t* As = sm;                          // [PSTAGES][BM][RSW]
    uint32_t* Bs = sm + PSTAGES * BM * RSW;

    const int z = blockIdx.z;
    const __half* A = z ? A1 : A0;
    const __half* Bw = z ? W1 : W0;
    const float* bias = z ? bias1 : bias0;

    const int tid = threadIdx.x;
    const int wid = tid >> 5, lane = tid & 31;
    const int g = lane >> 2, tg = lane & 3;
    const int wm0 = (wid & 3) * 32;    // 4 warps along M
    const int wn0 = (wid >> 2) * 64;   // 2 warps along N
    const int m0 = blockIdx.y * BM;
    const int n0 = blockIdx.x * BN;

    const uint32_t sA = smem_u32(As);
    const uint32_t sB = smem_u32(Bs);

    // loader mapping: 256 threads, 2 rows each (r, r+64), 16B chunk (tid&3)
    const int lrow = tid >> 2;
    const int lc = tid & 3;

    float c[2][8][4];
#pragma unroll
    for (int t = 0; t < 2; t++)
#pragma unroll
        for (int j = 0; j < 8; j++)
#pragma unroll
            for (int q = 0; q < 4; q++) c[t][j][q] = 0.0f;

    const __half* agb = A + (size_t)(m0 + lrow) * Hdim + lc * 8;
    const __half* bgb = Bw + (size_t)(n0 + lrow) * Hdim + lc * 8;
    const uint32_t dab = sA + (uint32_t)(lrow * RSW + lc * 4) * 4;
    const uint32_t dbb = sB + (uint32_t)(lrow * RSW + lc * 4) * 4;
    const uint32_t rowstep = 64 * RSW * 4;
    const uint32_t bufstep = BM * RSW * 4;

    // ldmatrix lane addressing: mi = matrix index, r = row within 8x8 matrix
    const int mi = lane >> 3, mr = lane & 7;
    // A: matrices (row-half = mi&1, k-half = mi>>1) for warp sub-tile t
    uint32_t aoff[2];
#pragma unroll
    for (int t = 0; t < 2; t++)
        aoff[t] = (uint32_t)(((wm0 + t * 16 + (mi & 1) * 8 + mr) * RSW + (mi >> 1) * 4) * 4);
    // B: matrices (j-sub = mi>>1, k-half = mi&1) for j-pair jp
    uint32_t boff[4];
#pragma unroll
    for (int jp = 0; jp < 4; jp++)
        boff[jp] = (uint32_t)(((wn0 + (jp * 2 + (mi >> 1)) * 8 + mr) * RSW + (mi & 1) * 4) * 4);

#define PREFETCH(kt) do { \
    const __half* _ag = agb + (kt) * BK; \
    const __half* _bg = bgb + (kt) * BK; \
    uint32_t _da = dab + ((kt) % PSTAGES) * bufstep; \
    uint32_t _db = dbb + ((kt) % PSTAGES) * bufstep; \
    asm volatile("cp.async.cg.shared.global [%0], [%1], 16;" \
        :: "r"(_da), "l"(_ag) : "memory"); \
    asm volatile("cp.async.cg.shared.global [%0], [%1], 16;" \
        :: "r"(_da + rowstep), "l"(_ag + (size_t)64 * Hdim) : "memory"); \
    asm volatile("cp.async.cg.shared.global [%0], [%1], 16;" \
        :: "r"(_db), "l"(_bg) : "memory"); \
    asm volatile("cp.async.cg.shared.global [%0], [%1], 16;" \
        :: "r"(_db + rowstep), "l"(_bg + (size_t)64 * Hdim) : "memory"); \
    asm volatile("cp.async.commit_group;" ::: "memory"); \
} while (0)

    PREFETCH(0);
    PREFETCH(1);
    PREFETCH(2);

    for (int kt = 0; kt < NKT; kt++) {
        asm volatile("cp.async.wait_group 2;" ::: "memory");
        __syncthreads();

        if (kt + 3 < NKT) PREFETCH(kt + 3);

        const uint32_t stA = sA + (kt % PSTAGES) * bufstep;
        const uint32_t stB = sB + (kt % PSTAGES) * bufstep;
#pragma unroll
        for (int ks = 0; ks < 2; ks++) {        // two k16 steps per BK=32
            const uint32_t ko = ks * 32;        // 8 words
            uint32_t a[2][4];
#pragma unroll
            for (int t = 0; t < 2; t++)
                LDSM_X4(a[t][0], a[t][1], a[t][2], a[t][3], stA + aoff[t] + ko);
#pragma unroll
            for (int jp = 0; jp < 4; jp++) {
                uint32_t b[4];
                LDSM_X4(b[0], b[1], b[2], b[3], stB + boff[jp] + ko);
#pragma unroll
                for (int t = 0; t < 2; t++) {
                    asm volatile(
                        "mma.sync.aligned.m16n8k16.row.col.f32.f16.f16.f32 "
                        "{%0,%1,%2,%3}, {%4,%5,%6,%7}, {%8,%9}, {%0,%1,%2,%3};"
                        : "+f"(c[t][jp * 2][0]), "+f"(c[t][jp * 2][1]),
                          "+f"(c[t][jp * 2][2]), "+f"(c[t][jp * 2][3])
                        : "r"(a[t][0]), "r"(a[t][1]), "r"(a[t][2]), "r"(a[t][3]),
                          "r"(b[0]), "r"(b[1]));
                    asm volatile(
                        "mma.sync.aligned.m16n8k16.row.col.f32.f16.f16.f32 "
                        "{%0,%1,%2,%3}, {%4,%5,%6,%7}, {%8,%9}, {%0,%1,%2,%3};"
                        : "+f"(c[t][jp * 2 + 1][0]), "+f"(c[t][jp * 2 + 1][1]),
                          "+f"(c[t][jp * 2 + 1][2]), "+f"(c[t][jp * 2 + 1][3])
                        : "r"(a[t][0]), "r"(a[t][1]), "r"(a[t][2]), "r"(a[t][3]),
                          "r"(b[2]), "r"(b[3]));
                }
            }
        }
        __syncthreads();
    }
#undef PREFETCH

    // epilogue
#pragma unroll
    for (int j = 0; j < 8; j++) {
        const int ncol = n0 + wn0 + j * 8 + tg * 2;
        const float bv0 = bias[ncol];
        const float bv1 = bias[ncol + 1];
#pragma unroll
        for (int t = 0; t < 2; t++) {
#pragma unroll
            for (int h = 0; h < 2; h++) {
                const int row = m0 + wm0 + t * 16 + g + h * 8;
                float v0 = c[t][j][h * 2 + 0] + bv0;
                float v1 = c[t][j][h * 2 + 1] + bv1;
                const int MODE = z ? M1 : M0;
                if (MODE == 0) {
                    __half2 hv = __floats2half2_rn(tanhf(v0), tanhf(v1));
                    __half* Ch = z ? H1 : H0;
                    *(__half2*)&Ch[(size_t)row * Hdim + ncol] = hv;
                } else {
                    if (MODE == 2) {
                        v0 = expf(-tanhf(v0));
                        v1 = expf(-tanhf(v1));
                    }
                    float* Cp = z ? P1 : P0;
                    *(float2*)&Cp[(size_t)row * Hdim + ncol] = make_float2(v0, v1);
                }
            }
        }
    }
}

// ------------- column moments of mu (deterministic two-stage) -------------------
__global__ __launch_bounds__(256) void col_moments_s1() {
    const int col = blockIdx.x * 256 + threadIdx.x;
    const int rc = blockIdx.y;
    float s = 0.0f, s2 = 0.0f;
    const int r0 = rc * 128;
#pragma unroll 4
    for (int r = 0; r < 128; r++) {
        float v = g_mu[(size_t)(r0 + r) * Hdim + col];
        s += v;
        s2 = fmaf(v, v, s2);
    }
    g_colpart[0][rc][col] = s;
    g_colpart[1][rc][col] = s2;
}

__global__ __launch_bounds__(256) void col_moments_s2() {
    const int col = blockIdx.x * 256 + threadIdx.x;
    float s = 0.0f, s2 = 0.0f;
    for (int rc = 0; rc < 64; rc++) {
        s += g_colpart[0][rc][col];
        s2 += g_colpart[1][rc][col];
    }
    const float invB = 1.0f / (float)Mdim;
    g_colmean[col] = s * invB;
    g_colsq[col] = s2 * invB;
}

__global__ __launch_bounds__(256) void final_elem(const float* __restrict__ modal_b) {
    __shared__ float shp[256];
    __shared__ float shd[256];
    const int tid = threadIdx.x;
    const size_t total = (size_t)Mdim * Hdim;
    const size_t stride = (size_t)gridDim.x * 256;
    size_t idx = (size_t)blockIdx.x * 256 + tid;

    float sp = 0.0f, sd = 0.0f;
    for (; idx < total; idx += stride) {
        int col = (int)(idx % Hdim);
        float mu = g_mu[idx];
        float iv = g_iv[idx];
        float mb = modal_b[idx];
        float dmb = mu - mb;
        float pos = -dmb * dmb * 0.5f * iv;
        float pair = g_colsq[col] - 2.0f * mu * g_colmean[col] + mu * mu;
        float neg = -pair * 0.5f * iv;
        sp += pos;
        sd += (pos - neg);
    }
    shp[tid] = sp;
    shd[tid] = sd;
    __syncthreads();
    for (int s = 128; s > 0; s >>= 1) {
        if (tid < s) { shp[tid] += shp[tid + s]; shd[tid] += shd[tid + s]; }
        __syncthreads();
    }
    if (tid == 0) {
        g_part[blockIdx.x * 2 + 0] = shp[0];
        g_part[blockIdx.x * 2 + 1] = shd[0];
    }
}

__global__ __launch_bounds__(256) void final_reduce(float* __restrict__ out, int nblocks) {
    __shared__ float shp[256];
    __shared__ float shd[256];
    const int tid = threadIdx.x;
    float sp = 0.0f, sd = 0.0f;
    for (int i = tid; i < nblocks; i += 256) {
        sp += g_part[i * 2 + 0];
        sd += g_part[i * 2 + 1];
    }
    shp[tid] = sp;
    shd[tid] = sd;
    __syncthreads();
    for (int s = 128; s > 0; s >>= 1) {
        if (tid < s) { shp[tid] += shp[tid + s]; shd[tid] += shd[tid + s]; }
        __syncthreads();
    }
    if (tid == 0) {
        const float invB = 1.0f / (float)Mdim;
        out[0] = shp[0] * invB;
        out[1] = shd[0] * invB;
    }
}

// --------------------------------- launcher --------------------------------------
extern "C" void kernel_launch(void* const* d_in, const int* in_sizes, int n_in,
                              void* d_out, int out_size) {
    const float* modal_a = (const float*)d_in[0];
    const float* modal_b = (const float*)d_in[1];
    const float* b1m = (const float*)d_in[3];
    const float* b2m = (const float*)d_in[5];
    const float* b1v = (const float*)d_in[7];
    const float* b2v = (const float*)d_in[9];
    float* out = (float*)d_out;

    __half *ah, *wh, *hm, *hv;
    float *mu, *iv;
    cudaGetSymbolAddress((void**)&ah, g_ah);
    cudaGetSymbolAddress((void**)&wh, g_wh);
    cudaGetSymbolAddress((void**)&hm, g_hm);
    cudaGetSymbolAddress((void**)&hv, g_hv);
    cudaGetSymbolAddress((void**)&mu, g_mu);
    cudaGetSymbolAddress((void**)&iv, g_iv);
    __half* w1m = wh + 0 * (size_t)Hdim * Hdim;
    __half* w1v = wh + 1 * (size_t)Hdim * Hdim;
    __half* w2m = wh + 2 * (size_t)Hdim * Hdim;
    __half* w2v = wh + 3 * (size_t)Hdim * Hdim;

    const int SMEM_BYTES = PSTAGES * (BM + BN) * RSW * 4;  // 81920
    cudaFuncSetAttribute((const void*)gemm_fused<0, 0>,
                         cudaFuncAttributeMaxDynamicSharedMemorySize, SMEM_BYTES);
    cudaFuncSetAttribute((const void*)gemm_fused<1, 2>,
                         cudaFuncAttributeMaxDynamicSharedMemorySize, SMEM_BYTES);

    pack_h<<<1024, 256>>>(modal_a, ah, Mdim * Hdim / 4);
    pack_w4<<<dim3(72, 4), 256>>>((const float*)d_in[2], (const float*)d_in[6],
                                  (const float*)d_in[4], (const float*)d_in[8], wh);

    dim3 ggrid(Hdim / BN, Mdim / BM, 2);   // (6, 64, 2) = 768 CTAs per layer
    gemm_fused<0, 0><<<ggrid, 256, SMEM_BYTES>>>(ah, ah, w1m, w1v, b1m, b1v,
                                                 nullptr, nullptr, hm, hv);
    gemm_fused<1, 2><<<ggrid, 256, SMEM_BYTES>>>(hm, hv, w2m, w2v, b2m, b2v,
                                                 mu, iv, nullptr, nullptr);

    col_moments_s1<<<dim3(3, 64), 256>>>();
    col_moments_s2<<<dim3(3), 256>>>();
    final_elem<<<4096, 256>>>(modal_b);
    final_reduce<<<1, 256>>>(out, 4096);
}

// round 7
// speedup vs baseline: 6.9206x; 1.0154x over previous
#include <cuda_runtime.h>
#include <cuda_fp16.h>
#include <cstdint>
#include <math.h>

#define Mdim 8192
#define Hdim 768
#define BM 128
#define BN 128
#define BK 32
#define RSW 20          // smem row stride in 32-bit words (40 halves)
#define NKT (Hdim / BK) // 24
#define PSTAGES 5       // cp.async pipeline depth (4 in flight)
#define NTILE_X (Hdim / BN)   // 6
#define NTILE_Y (Mdim / BM)   // 64
#define TOT_TILES (NTILE_X * NTILE_Y * 2)  // 768
#define PGRID 296       // persistent grid: 2 CTAs/SM * 148

// ---------------- scratch (static device globals; no allocation) ----------------
__device__ __half g_ah[Mdim * Hdim];     // fp16 modal_a
__device__ __half g_wh[4][Hdim * Hdim];  // fp16 W1m, W1v, W2m, W2v
__device__ __half g_hm[Mdim * Hdim];     // fp16 tanh(layer1m)
__device__ __half g_hv[Mdim * Hdim];     // fp16 tanh(layer1v)
__device__ float g_mu[Mdim * Hdim];
__device__ float g_iv[Mdim * Hdim];
__device__ float g_colpart[2][NTILE_Y][Hdim];
__device__ float g_colmean[Hdim];
__device__ float g_colsq[Hdim];
__device__ float g_part[4096 * 2];

// ---------------------------- helpers -------------------------------------------
__device__ __forceinline__ uint32_t smem_u32(const void* p) {
    uint32_t a;
    asm("{ .reg .u64 t; cvta.to.shared.u64 t, %1; cvt.u32.u64 %0, t; }"
        : "=r"(a) : "l"(p));
    return a;
}
__device__ __forceinline__ float tanh_fast(float x) {
    float y;
    asm("tanh.approx.f32 %0, %1;" : "=f"(y) : "f"(x));
    return y;
}
#define LDSM_X4(r0, r1, r2, r3, addr) \
    asm volatile("ldmatrix.sync.aligned.m8n8.x4.shared.b16 {%0,%1,%2,%3}, [%4];" \
        : "=r"(r0), "=r"(r1), "=r"(r2), "=r"(r3) : "r"(addr))

// -------------------- pack: modal_a + all 4 weights, one launch ------------------
__global__ __launch_bounds__(256) void pack_all(
    const float* __restrict__ a,
    const float* __restrict__ w0, const float* __restrict__ w1,
    const float* __restrict__ w2, const float* __restrict__ w3,
    __half* __restrict__ ah, __half* __restrict__ wh) {
    const int na = Mdim * Hdim / 4;          // 1572864
    const int nw = Hdim * Hdim / 4;          // 147456
    const int total = na + 4 * nw;
    for (int i = blockIdx.x * 256 + threadIdx.x; i < total; i += gridDim.x * 256) {
        const float* src;
        __half* dst;
        int idx;
        if (i < na) { src = a; dst = ah; idx = i; }
        else {
            int r = i - na;
            int wsel = r / nw;
            idx = r - wsel * nw;
            src = (wsel == 0) ? w0 : (wsel == 1) ? w1 : (wsel == 2) ? w2 : w3;
            dst = wh + (size_t)wsel * Hdim * Hdim;
        }
        float4 v = ((const float4*)src)[idx];
        __half2 h0 = __floats2half2_rn(v.x, v.y);
        __half2 h1 = __floats2half2_rn(v.z, v.w);
        *(uint2*)(dst + (size_t)idx * 4) =
            make_uint2(*(uint32_t*)&h0, *(uint32_t*)&h1);
    }
}

// -------------------- persistent fused dual-branch fp16 GEMM --------------------
// tile = z*384 + by*6 + bx ;  z selects branch (A/W/bias/output)
// MODE 0: tanh.approx -> half store   MODE 1: identity -> fp32 + column partials
// MODE 2: exp(-tanh) -> fp32
template <int M0, int M1>
__global__ __launch_bounds__(256, 2) void gemm_fused(
    const __half* __restrict__ A0, const __half* __restrict__ A1,
    const __half* __restrict__ W0, const __half* __restrict__ W1,
    const float* __restrict__ bias0, const float* __restrict__ bias1,
    float* __restrict__ P0, float* __restrict__ P1,
    __half* __restrict__ H0, __half* __restrict__ H1)
{
    extern __shared__ uint32_t sm[];
    const uint32_t sA = smem_u32(sm);
    const uint32_t sB = sA + PSTAGES * BM * RSW * 4;

    const int tid = threadIdx.x;
    const int wid = tid >> 5, lane = tid & 31;
    const int g = lane >> 2, tg = lane & 3;
    const int wm0 = (wid & 3) * 32;    // 4 warps along M
    const int wn0 = (wid >> 2) * 64;   // 2 warps along N

    // loader mapping: 2 rows each (r, r+64), 16B chunk (tid&3)
    const int lrow = tid >> 2;
    const int lc = tid & 3;
    const uint32_t dab = sA + (uint32_t)(lrow * RSW + lc * 4) * 4;
    const uint32_t dbb = sB + (uint32_t)(lrow * RSW + lc * 4) * 4;
    const uint32_t rowstep = 64 * RSW * 4;
    const uint32_t bufstep = BM * RSW * 4;

    // ldmatrix lane addressing
    const int mi = lane >> 3, mr = lane & 7;
    uint32_t aoff[2];
#pragma unroll
    for (int t = 0; t < 2; t++)
        aoff[t] = (uint32_t)(((wm0 + t * 16 + (mi & 1) * 8 + mr) * RSW + (mi >> 1) * 4) * 4);
    uint32_t boff[4];
#pragma unroll
    for (int jp = 0; jp < 4; jp++)
        boff[jp] = (uint32_t)(((wn0 + (jp * 2 + (mi >> 1)) * 8 + mr) * RSW + (mi & 1) * 4) * 4);

    float* sS = (float*)sm;          // [4][128] reduction overlay (mode 1 only)
    float* sQ = sS + 512;

    for (int tile = blockIdx.x; tile < TOT_TILES; tile += PGRID) {
        const int z = (tile >= NTILE_X * NTILE_Y) ? 1 : 0;
        const int r = tile - z * NTILE_X * NTILE_Y;
        const int by = r / NTILE_X;
        const int bx = r - by * NTILE_X;
        const int m0 = by * BM;
        const int n0 = bx * BN;
        const int MODE = z ? M1 : M0;

        const __half* A = z ? A1 : A0;
        const __half* Bw = z ? W1 : W0;
        const float* bias = z ? bias1 : bias0;

        const __half* agb = A + (size_t)(m0 + lrow) * Hdim + lc * 8;
        const __half* bgb = Bw + (size_t)(n0 + lrow) * Hdim + lc * 8;

        float c[2][8][4];
#pragma unroll
        for (int t = 0; t < 2; t++)
#pragma unroll
            for (int j = 0; j < 8; j++)
#pragma unroll
                for (int q = 0; q < 4; q++) c[t][j][q] = 0.0f;

#define PREFETCH(kt) do { \
    const __half* _ag = agb + (kt) * BK; \
    const __half* _bg = bgb + (kt) * BK; \
    uint32_t _da = dab + ((kt) % PSTAGES) * bufstep; \
    uint32_t _db = dbb + ((kt) % PSTAGES) * bufstep; \
    asm volatile("cp.async.cg.shared.global [%0], [%1], 16;" \
        :: "r"(_da), "l"(_ag) : "memory"); \
    asm volatile("cp.async.cg.shared.global [%0], [%1], 16;" \
        :: "r"(_da + rowstep), "l"(_ag + (size_t)64 * Hdim) : "memory"); \
    asm volatile("cp.async.cg.shared.global [%0], [%1], 16;" \
        :: "r"(_db), "l"(_bg) : "memory"); \
    asm volatile("cp.async.cg.shared.global [%0], [%1], 16;" \
        :: "r"(_db + rowstep), "l"(_bg + (size_t)64 * Hdim) : "memory"); \
    asm volatile("cp.async.commit_group;" ::: "memory"); \
} while (0)

        PREFETCH(0);
        PREFETCH(1);
        PREFETCH(2);
        PREFETCH(3);

        for (int kt = 0; kt < NKT; kt++) {
            asm volatile("cp.async.wait_group 3;" ::: "memory");
            __syncthreads();

            // keep group count aligned so wait_group 3 always covers group kt
            if (kt + 4 < NKT) PREFETCH(kt + 4);
            else asm volatile("cp.async.commit_group;" ::: "memory");

            const uint32_t stA = sA + (kt % PSTAGES) * bufstep;
            const uint32_t stB = sB + (kt % PSTAGES) * bufstep;
#pragma unroll
            for (int ks = 0; ks < 2; ks++) {
                const uint32_t ko = ks * 32;
                uint32_t a[2][4];
#pragma unroll
                for (int t = 0; t < 2; t++)
                    LDSM_X4(a[t][0], a[t][1], a[t][2], a[t][3], stA + aoff[t] + ko);
#pragma unroll
                for (int jp = 0; jp < 4; jp++) {
                    uint32_t b[4];
                    LDSM_X4(b[0], b[1], b[2], b[3], stB + boff[jp] + ko);
#pragma unroll
                    for (int t = 0; t < 2; t++) {
                        asm volatile(
                            "mma.sync.aligned.m16n8k16.row.col.f32.f16.f16.f32 "
                            "{%0,%1,%2,%3}, {%4,%5,%6,%7}, {%8,%9}, {%0,%1,%2,%3};"
                            : "+f"(c[t][jp * 2][0]), "+f"(c[t][jp * 2][1]),
                              "+f"(c[t][jp * 2][2]), "+f"(c[t][jp * 2][3])
                            : "r"(a[t][0]), "r"(a[t][1]), "r"(a[t][2]), "r"(a[t][3]),
                              "r"(b[0]), "r"(b[1]));
                        asm volatile(
                            "mma.sync.aligned.m16n8k16.row.col.f32.f16.f16.f32 "
                            "{%0,%1,%2,%3}, {%4,%5,%6,%7}, {%8,%9}, {%0,%1,%2,%3};"
                            : "+f"(c[t][jp * 2 + 1][0]), "+f"(c[t][jp * 2 + 1][1]),
                              "+f"(c[t][jp * 2 + 1][2]), "+f"(c[t][jp * 2 + 1][3])
                            : "r"(a[t][0]), "r"(a[t][1]), "r"(a[t][2]), "r"(a[t][3]),
                              "r"(b[2]), "r"(b[3]));
                    }
                }
            }
        }
#undef PREFETCH

        // -------- epilogue --------
        if (MODE == 1) __syncthreads();   // protect smem overlay vs last LDSM reads
#pragma unroll
        for (int j = 0; j < 8; j++) {
            const int ncol = n0 + wn0 + j * 8 + tg * 2;
            const float bv0 = bias[ncol];
            const float bv1 = bias[ncol + 1];
            float s0 = 0.f, s1 = 0.f, q0 = 0.f, q1 = 0.f;
#pragma unroll
            for (int t = 0; t < 2; t++) {
#pragma unroll
                for (int h = 0; h < 2; h++) {
                    const int row = m0 + wm0 + t * 16 + g + h * 8;
                    float v0 = c[t][j][h * 2 + 0] + bv0;
                    float v1 = c[t][j][h * 2 + 1] + bv1;
                    if (MODE == 0) {
                        __half2 hv = __floats2half2_rn(tanh_fast(v0), tanh_fast(v1));
                        __half* Ch = z ? H1 : H0;
                        *(__half2*)&Ch[(size_t)row * Hdim + ncol] = hv;
                    } else {
                        if (MODE == 2) {
                            v0 = __expf(-tanhf(v0));
                            v1 = __expf(-tanhf(v1));
                        }
                        float* Cp = z ? P1 : P0;
                        *(float2*)&Cp[(size_t)row * Hdim + ncol] = make_float2(v0, v1);
                        if (MODE == 1) {
                            s0 += v0; q0 = fmaf(v0, v0, q0);
                            s1 += v1; q1 = fmaf(v1, v1, q1);
                        }
                    }
                }
            }
            if (MODE == 1) {
                // reduce over g (lanes differ by bits 2,3,4)
#pragma unroll
                for (int msk = 4; msk <= 16; msk <<= 1) {
                    s0 += __shfl_xor_sync(0xffffffffu, s0, msk);
                    q0 += __shfl_xor_sync(0xffffffffu, q0, msk);
                    s1 += __shfl_xor_sync(0xffffffffu, s1, msk);
                    q1 += __shfl_xor_sync(0xffffffffu, q1, msk);
                }
                if (lane < 4) {
                    const int cl = wn0 + j * 8 + tg * 2;
                    const int mw = wid & 3;
                    sS[mw * 128 + cl] = s0; sQ[mw * 128 + cl] = q0;
                    sS[mw * 128 + cl + 1] = s1; sQ[mw * 128 + cl + 1] = q1;
                }
            }
        }
        if (MODE == 1) {
            __syncthreads();
            if (tid < 128) {
                const int cl = tid;
                float s = sS[cl] + sS[128 + cl] + sS[256 + cl] + sS[384 + cl];
                g_colpart[0][by][n0 + cl] = s;
            } else {
                const int cl = tid - 128;
                float q = sQ[cl] + sQ[128 + cl] + sQ[256 + cl] + sQ[384 + cl];
                g_colpart[1][by][n0 + cl] = q;
            }
        }
        __syncthreads();   // end-of-tile: protect smem vs next tile's prefetch
    }
}

// ------------- column moments: final deterministic sum over 64 chunks ------------
__global__ __launch_bounds__(256) void col_moments_s2() {
    const int col = blockIdx.x * 256 + threadIdx.x;
    float s = 0.0f, s2 = 0.0f;
    for (int rc = 0; rc < NTILE_Y; rc++) {
        s += g_colpart[0][rc][col];
        s2 += g_colpart[1][rc][col];
    }
    const float invB = 1.0f / (float)Mdim;
    g_colmean[col] = s * invB;
    g_colsq[col] = s2 * invB;
}

__global__ __launch_bounds__(256) void final_elem(const float* __restrict__ modal_b) {
    __shared__ float shp[256];
    __shared__ float shd[256];
    const int tid = threadIdx.x;
    const size_t total = (size_t)Mdim * Hdim;
    const size_t stride = (size_t)gridDim.x * 256;
    size_t idx = (size_t)blockIdx.x * 256 + tid;

    float sp = 0.0f, sd = 0.0f;
    for (; idx < total; idx += stride) {
        int col = (int)(idx % Hdim);
        float mu = g_mu[idx];
        float iv = g_iv[idx];
        float mb = modal_b[idx];
        float dmb = mu - mb;
        float pos = -dmb * dmb * 0.5f * iv;
        float pair = g_colsq[col] - 2.0f * mu * g_colmean[col] + mu * mu;
        float neg = -pair * 0.5f * iv;
        sp += pos;
        sd += (pos - neg);
    }
    shp[tid] = sp;
    shd[tid] = sd;
    __syncthreads();
    for (int s = 128; s > 0; s >>= 1) {
        if (tid < s) { shp[tid] += shp[tid + s]; shd[tid] += shd[tid + s]; }
        __syncthreads();
    }
    if (tid == 0) {
        g_part[blockIdx.x * 2 + 0] = shp[0];
        g_part[blockIdx.x * 2 + 1] = shd[0];
    }
}

__global__ __launch_bounds__(256) void final_reduce(float* __restrict__ out, int nblocks) {
    __shared__ float shp[256];
    __shared__ float shd[256];
    const int tid = threadIdx.x;
    float sp = 0.0f, sd = 0.0f;
    for (int i = tid; i < nblocks; i += 256) {
        sp += g_part[i * 2 + 0];
        sd += g_part[i * 2 + 1];
    }
    shp[tid] = sp;
    shd[tid] = sd;
    __syncthreads();
    for (int s = 128; s > 0; s >>= 1) {
        if (tid < s) { shp[tid] += shp[tid + s]; shd[tid] += shd[tid + s]; }
        __syncthreads();
    }
    if (tid == 0) {
        const float invB = 1.0f / (float)Mdim;
        out[0] = shp[0] * invB;
        out[1] = shd[0] * invB;
    }
}

// --------------------------------- launcher --------------------------------------
extern "C" void kernel_launch(void* const* d_in, const int* in_sizes, int n_in,
                              void* d_out, int out_size) {
    const float* modal_a = (const float*)d_in[0];
    const float* modal_b = (const float*)d_in[1];
    const float* b1m = (const float*)d_in[3];
    const float* b2m = (const float*)d_in[5];
    const float* b1v = (const float*)d_in[7];
    const float* b2v = (const float*)d_in[9];
    float* out = (float*)d_out;

    __half *ah, *wh, *hm, *hv;
    float *mu, *iv;
    cudaGetSymbolAddress((void**)&ah, g_ah);
    cudaGetSymbolAddress((void**)&wh, g_wh);
    cudaGetSymbolAddress((void**)&hm, g_hm);
    cudaGetSymbolAddress((void**)&hv, g_hv);
    cudaGetSymbolAddress((void**)&mu, g_mu);
    cudaGetSymbolAddress((void**)&iv, g_iv);
    __half* w1m = wh + 0 * (size_t)Hdim * Hdim;
    __half* w1v = wh + 1 * (size_t)Hdim * Hdim;
    __half* w2m = wh + 2 * (size_t)Hdim * Hdim;
    __half* w2v = wh + 3 * (size_t)Hdim * Hdim;

    const int SMEM_BYTES = PSTAGES * (BM + BN) * RSW * 4;  // 102400
    cudaFuncSetAttribute((const void*)gemm_fused<0, 0>,
                         cudaFuncAttributeMaxDynamicSharedMemorySize, SMEM_BYTES);
    cudaFuncSetAttribute((const void*)gemm_fused<1, 2>,
                         cudaFuncAttributeMaxDynamicSharedMemorySize, SMEM_BYTES);

    pack_all<<<1184, 256>>>(modal_a, (const float*)d_in[2], (const float*)d_in[6],
                            (const float*)d_in[4], (const float*)d_in[8], ah, wh);

    gemm_fused<0, 0><<<PGRID, 256, SMEM_BYTES>>>(ah, ah, w1m, w1v, b1m, b1v,
                                                 nullptr, nullptr, hm, hv);
    gemm_fused<1, 2><<<PGRID, 256, SMEM_BYTES>>>(hm, hv, w2m, w2v, b2m, b2v,
                                                 mu, iv, nullptr, nullptr);

    col_moments_s2<<<3, 256>>>();
    final_elem<<<1184, 256>>>(modal_b);
    final_reduce<<<1, 256>>>(out, 1184);
}

// round 8
// speedup vs baseline: 7.2171x; 1.0429x over previous
#include <cuda_runtime.h>
#include <cuda_fp16.h>
#include <cstdint>
#include <math.h>

#define Mdim 8192
#define Hdim 768
#define BM 128
#define BN 64
#define BK 32
#define RSW 20          // smem row stride in 32-bit words (40 halves)
#define NKT (Hdim / BK) // 24
#define PSTAGES 4       // cp.async pipeline depth (3 in flight)
#define NTILE_X (Hdim / BN)   // 12
#define NTILE_Y (Mdim / BM)   // 64
#define TOT_TILES (NTILE_X * NTILE_Y * 2)  // 1536
#define PGRID 444       // persistent grid: 3 CTAs/SM * 148

// ---------------- scratch (static device globals; no allocation) ----------------
__device__ __half g_ah[Mdim * Hdim];     // fp16 modal_a
__device__ __half g_wh[4][Hdim * Hdim];  // fp16 W1m, W1v, W2m, W2v
__device__ __half g_hm[Mdim * Hdim];     // fp16 tanh(layer1m)
__device__ __half g_hv[Mdim * Hdim];     // fp16 tanh(layer1v)
__device__ float g_mu[Mdim * Hdim];
__device__ float g_iv[Mdim * Hdim];
__device__ float g_colpart[2][NTILE_Y][Hdim];
__device__ float g_colmean[Hdim];
__device__ float g_colsq[Hdim];
__device__ float g_part[4096 * 2];

// ---------------------------- helpers -------------------------------------------
__device__ __forceinline__ uint32_t smem_u32(const void* p) {
    uint32_t a;
    asm("{ .reg .u64 t; cvta.to.shared.u64 t, %1; cvt.u32.u64 %0, t; }"
        : "=r"(a) : "l"(p));
    return a;
}
__device__ __forceinline__ float tanh_fast(float x) {
    float y;
    asm("tanh.approx.f32 %0, %1;" : "=f"(y) : "f"(x));
    return y;
}
#define LDSM_X4(r0, r1, r2, r3, addr) \
    asm volatile("ldmatrix.sync.aligned.m8n8.x4.shared.b16 {%0,%1,%2,%3}, [%4];" \
        : "=r"(r0), "=r"(r1), "=r"(r2), "=r"(r3) : "r"(addr))

// -------------------- pack: modal_a + all 4 weights, one launch ------------------
__global__ __launch_bounds__(256) void pack_all(
    const float* __restrict__ a,
    const float* __restrict__ w0, const float* __restrict__ w1,
    const float* __restrict__ w2, const float* __restrict__ w3,
    __half* __restrict__ ah, __half* __restrict__ wh) {
    const int na = Mdim * Hdim / 4;
    const int nw = Hdim * Hdim / 4;
    const int total = na + 4 * nw;
    for (int i = blockIdx.x * 256 + threadIdx.x; i < total; i += gridDim.x * 256) {
        const float* src;
        __half* dst;
        int idx;
        if (i < na) { src = a; dst = ah; idx = i; }
        else {
            int r = i - na;
            int wsel = r / nw;
            idx = r - wsel * nw;
            src = (wsel == 0) ? w0 : (wsel == 1) ? w1 : (wsel == 2) ? w2 : w3;
            dst = wh + (size_t)wsel * Hdim * Hdim;
        }
        float4 v = ((const float4*)src)[idx];
        __half2 h0 = __floats2half2_rn(v.x, v.y);
        __half2 h1 = __floats2half2_rn(v.z, v.w);
        *(uint2*)(dst + (size_t)idx * 4) =
            make_uint2(*(uint32_t*)&h0, *(uint32_t*)&h1);
    }
}

// -------------------- persistent fused dual-branch fp16 GEMM --------------------
// BM=128 x BN=64 tile, 8 warps (4 along M, 2 along N), 3 CTAs/SM.
// MODE 0: tanh.approx -> half store   MODE 1: identity -> fp32 + column partials
// MODE 2: exp(-tanh) -> fp32
template <int M0, int M1>
__global__ __launch_bounds__(256, 3) void gemm_fused(
    const __half* __restrict__ A0, const __half* __restrict__ A1,
    const __half* __restrict__ W0, const __half* __restrict__ W1,
    const float* __restrict__ bias0, const float* __restrict__ bias1,
    float* __restrict__ P0, float* __restrict__ P1,
    __half* __restrict__ H0, __half* __restrict__ H1)
{
    extern __shared__ uint32_t sm[];
    const uint32_t sA = smem_u32(sm);
    const uint32_t sB = sA + PSTAGES * BM * RSW * 4;

    const int tid = threadIdx.x;
    const int wid = tid >> 5, lane = tid & 31;
    const int g = lane >> 2, tg = lane & 3;
    const int wm0 = (wid & 3) * 32;    // 4 warps along M
    const int wn0 = (wid >> 2) * 32;   // 2 warps along N

    // loader mapping: A rows (lrow, lrow+64) chunk lc; B row lrow chunk lc
    const int lrow = tid >> 2;
    const int lc = tid & 3;
    const uint32_t dab = sA + (uint32_t)(lrow * RSW + lc * 4) * 4;
    const uint32_t dbb = sB + (uint32_t)(lrow * RSW + lc * 4) * 4;
    const uint32_t rowstep = 64 * RSW * 4;
    const uint32_t abufstep = BM * RSW * 4;
    const uint32_t bbufstep = BN * RSW * 4;

    // ldmatrix lane addressing
    const int mi = lane >> 3, mr = lane & 7;
    uint32_t aoff[2];
#pragma unroll
    for (int t = 0; t < 2; t++)
        aoff[t] = (uint32_t)(((wm0 + t * 16 + (mi & 1) * 8 + mr) * RSW + (mi >> 1) * 4) * 4);
    uint32_t boff[2];
#pragma unroll
    for (int jp = 0; jp < 2; jp++)
        boff[jp] = (uint32_t)(((wn0 + (jp * 2 + (mi >> 1)) * 8 + mr) * RSW + (mi & 1) * 4) * 4);

    float* sS = (float*)sm;          // [4][64] reduction overlay (mode 1 only)
    float* sQ = sS + 256;

    for (int tile = blockIdx.x; tile < TOT_TILES; tile += PGRID) {
        const int z = (tile >= NTILE_X * NTILE_Y) ? 1 : 0;
        const int r = tile - z * NTILE_X * NTILE_Y;
        const int by = r / NTILE_X;
        const int bx = r - by * NTILE_X;
        const int m0 = by * BM;
        const int n0 = bx * BN;
        const int MODE = z ? M1 : M0;

        const __half* A = z ? A1 : A0;
        const __half* Bw = z ? W1 : W0;
        const float* bias = z ? bias1 : bias0;

        const __half* agb = A + (size_t)(m0 + lrow) * Hdim + lc * 8;
        const __half* bgb = Bw + (size_t)(n0 + lrow) * Hdim + lc * 8;

        float c[2][4][4];
#pragma unroll
        for (int t = 0; t < 2; t++)
#pragma unroll
            for (int j = 0; j < 4; j++)
#pragma unroll
                for (int q = 0; q < 4; q++) c[t][j][q] = 0.0f;

#define PREFETCH(kt) do { \
    const __half* _ag = agb + (kt) * BK; \
    const __half* _bg = bgb + (kt) * BK; \
    uint32_t _da = dab + ((kt) % PSTAGES) * abufstep; \
    uint32_t _db = dbb + ((kt) % PSTAGES) * bbufstep; \
    asm volatile("cp.async.cg.shared.global [%0], [%1], 16;" \
        :: "r"(_da), "l"(_ag) : "memory"); \
    asm volatile("cp.async.cg.shared.global [%0], [%1], 16;" \
        :: "r"(_da + rowstep), "l"(_ag + (size_t)64 * Hdim) : "memory"); \
    if (lrow < BN) \
        asm volatile("cp.async.cg.shared.global [%0], [%1], 16;" \
            :: "r"(_db), "l"(_bg) : "memory"); \
    asm volatile("cp.async.commit_group;" ::: "memory"); \
} while (0)

        PREFETCH(0);
        PREFETCH(1);
        PREFETCH(2);

        for (int kt = 0; kt < NKT; kt++) {
            asm volatile("cp.async.wait_group 2;" ::: "memory");
            __syncthreads();

            if (kt + 3 < NKT) PREFETCH(kt + 3);
            else asm volatile("cp.async.commit_group;" ::: "memory");

            const uint32_t stA = sA + (kt % PSTAGES) * abufstep;
            const uint32_t stB = sB + (kt % PSTAGES) * bbufstep;
#pragma unroll
            for (int ks = 0; ks < 2; ks++) {
                const uint32_t ko = ks * 32;
                uint32_t a[2][4];
#pragma unroll
                for (int t = 0; t < 2; t++)
                    LDSM_X4(a[t][0], a[t][1], a[t][2], a[t][3], stA + aoff[t] + ko);
#pragma unroll
                for (int jp = 0; jp < 2; jp++) {
                    uint32_t b[4];
                    LDSM_X4(b[0], b[1], b[2], b[3], stB + boff[jp] + ko);
#pragma unroll
                    for (int t = 0; t < 2; t++) {
                        asm volatile(
                            "mma.sync.aligned.m16n8k16.row.col.f32.f16.f16.f32 "
                            "{%0,%1,%2,%3}, {%4,%5,%6,%7}, {%8,%9}, {%0,%1,%2,%3};"
                            : "+f"(c[t][jp * 2][0]), "+f"(c[t][jp * 2][1]),
                              "+f"(c[t][jp * 2][2]), "+f"(c[t][jp * 2][3])
                            : "r"(a[t][0]), "r"(a[t][1]), "r"(a[t][2]), "r"(a[t][3]),
                              "r"(b[0]), "r"(b[1]));
                        asm volatile(
                            "mma.sync.aligned.m16n8k16.row.col.f32.f16.f16.f32 "
                            "{%0,%1,%2,%3}, {%4,%5,%6,%7}, {%8,%9}, {%0,%1,%2,%3};"
                            : "+f"(c[t][jp * 2 + 1][0]), "+f"(c[t][jp * 2 + 1][1]),
                              "+f"(c[t][jp * 2 + 1][2]), "+f"(c[t][jp * 2 + 1][3])
                            : "r"(a[t][0]), "r"(a[t][1]), "r"(a[t][2]), "r"(a[t][3]),
                              "r"(b[2]), "r"(b[3]));
                    }
                }
            }
        }
#undef PREFETCH

        // -------- epilogue --------
        if (MODE == 1) __syncthreads();   // protect smem overlay
#pragma unroll
        for (int j = 0; j < 4; j++) {
            const int ncol = n0 + wn0 + j * 8 + tg * 2;
            const float bv0 = bias[ncol];
            const float bv1 = bias[ncol + 1];
            float s0 = 0.f, s1 = 0.f, q0 = 0.f, q1 = 0.f;
#pragma unroll
            for (int t = 0; t < 2; t++) {
#pragma unroll
                for (int h = 0; h < 2; h++) {
                    const int row = m0 + wm0 + t * 16 + g + h * 8;
                    float v0 = c[t][j][h * 2 + 0] + bv0;
                    float v1 = c[t][j][h * 2 + 1] + bv1;
                    if (MODE == 0) {
                        __half2 hv = __floats2half2_rn(tanh_fast(v0), tanh_fast(v1));
                        __half* Ch = z ? H1 : H0;
                        *(__half2*)&Ch[(size_t)row * Hdim + ncol] = hv;
                    } else {
                        if (MODE == 2) {
                            v0 = __expf(-tanhf(v0));
                            v1 = __expf(-tanhf(v1));
                        }
                        float* Cp = z ? P1 : P0;
                        *(float2*)&Cp[(size_t)row * Hdim + ncol] = make_float2(v0, v1);
                        if (MODE == 1) {
                            s0 += v0; q0 = fmaf(v0, v0, q0);
                            s1 += v1; q1 = fmaf(v1, v1, q1);
                        }
                    }
                }
            }
            if (MODE == 1) {
#pragma unroll
                for (int msk = 4; msk <= 16; msk <<= 1) {
                    s0 += __shfl_xor_sync(0xffffffffu, s0, msk);
                    q0 += __shfl_xor_sync(0xffffffffu, q0, msk);
                    s1 += __shfl_xor_sync(0xffffffffu, s1, msk);
                    q1 += __shfl_xor_sync(0xffffffffu, q1, msk);
                }
                if (lane < 4) {
                    const int cl = wn0 + j * 8 + tg * 2;
                    const int mw = wid & 3;
                    sS[mw * 64 + cl] = s0; sQ[mw * 64 + cl] = q0;
                    sS[mw * 64 + cl + 1] = s1; sQ[mw * 64 + cl + 1] = q1;
                }
            }
        }
        if (MODE == 1) {
            __syncthreads();
            if (tid < 64) {
                const int cl = tid;
                g_colpart[0][by][n0 + cl] =
                    sS[cl] + sS[64 + cl] + sS[128 + cl] + sS[192 + cl];
            } else if (tid < 128) {
                const int cl = tid - 64;
                g_colpart[1][by][n0 + cl] =
                    sQ[cl] + sQ[64 + cl] + sQ[128 + cl] + sQ[192 + cl];
            }
        }
        __syncthreads();   // end-of-tile: protect smem vs next tile's prefetch
    }
}

// ------------- column moments: parallel deterministic sum over 64 chunks ---------
// 24 blocks x 256 threads; 8 threads per column, each sums 8 chunks, shfl reduce.
__global__ __launch_bounds__(256) void col_moments_s2() {
    const int col = blockIdx.x * 32 + (threadIdx.x >> 3);
    const int sub = threadIdx.x & 7;
    float s = 0.0f, s2 = 0.0f;
#pragma unroll
    for (int k = 0; k < 8; k++) {
        int rc = sub * 8 + k;
        s += g_colpart[0][rc][col];
        s2 += g_colpart[1][rc][col];
    }
#pragma unroll
    for (int msk = 4; msk >= 1; msk >>= 1) {
        s += __shfl_xor_sync(0xffffffffu, s, msk);
        s2 += __shfl_xor_sync(0xffffffffu, s2, msk);
    }
    if (sub == 0) {
        const float invB = 1.0f / (float)Mdim;
        g_colmean[col] = s * invB;
        g_colsq[col] = s2 * invB;
    }
}

__global__ __launch_bounds__(256) void final_elem(const float* __restrict__ modal_b) {
    __shared__ float shp[256];
    __shared__ float shd[256];
    const int tid = threadIdx.x;
    const size_t total = (size_t)Mdim * Hdim;
    const size_t stride = (size_t)gridDim.x * 256;
    size_t idx = (size_t)blockIdx.x * 256 + tid;

    float sp = 0.0f, sd = 0.0f;
    for (; idx < total; idx += stride) {
        int col = (int)(idx % Hdim);
        float mu = g_mu[idx];
        float iv = g_iv[idx];
        float mb = modal_b[idx];
        float dmb = mu - mb;
        float pos = -dmb * dmb * 0.5f * iv;
        float pair = g_colsq[col] - 2.0f * mu * g_colmean[col] + mu * mu;
        float neg = -pair * 0.5f * iv;
        sp += pos;
        sd += (pos - neg);
    }
    shp[tid] = sp;
    shd[tid] = sd;
    __syncthreads();
    for (int s = 128; s > 0; s >>= 1) {
        if (tid < s) { shp[tid] += shp[tid + s]; shd[tid] += shd[tid + s]; }
        __syncthreads();
    }
    if (tid == 0) {
        g_part[blockIdx.x * 2 + 0] = shp[0];
        g_part[blockIdx.x * 2 + 1] = shd[0];
    }
}

__global__ __launch_bounds__(256) void final_reduce(float* __restrict__ out, int nblocks) {
    __shared__ float shp[256];
    __shared__ float shd[256];
    const int tid = threadIdx.x;
    float sp = 0.0f, sd = 0.0f;
    for (int i = tid; i < nblocks; i += 256) {
        sp += g_part[i * 2 + 0];
        sd += g_part[i * 2 + 1];
    }
    shp[tid] = sp;
    shd[tid] = sd;
    __syncthreads();
    for (int s = 128; s > 0; s >>= 1) {
        if (tid < s) { shp[tid] += shp[tid + s]; shd[tid] += shd[tid + s]; }
        __syncthreads();
    }
    if (tid == 0) {
        const float invB = 1.0f / (float)Mdim;
        out[0] = shp[0] * invB;
        out[1] = shd[0] * invB;
    }
}

// --------------------------------- launcher --------------------------------------
extern "C" void kernel_launch(void* const* d_in, const int* in_sizes, int n_in,
                              void* d_out, int out_size) {
    const float* modal_a = (const float*)d_in[0];
    const float* modal_b = (const float*)d_in[1];
    const float* b1m = (const float*)d_in[3];
    const float* b2m = (const float*)d_in[5];
    const float* b1v = (const float*)d_in[7];
    const float* b2v = (const float*)d_in[9];
    float* out = (float*)d_out;

    __half *ah, *wh, *hm, *hv;
    float *mu, *iv;
    cudaGetSymbolAddress((void**)&ah, g_ah);
    cudaGetSymbolAddress((void**)&wh, g_wh);
    cudaGetSymbolAddress((void**)&hm, g_hm);
    cudaGetSymbolAddress((void**)&hv, g_hv);
    cudaGetSymbolAddress((void**)&mu, g_mu);
    cudaGetSymbolAddress((void**)&iv, g_iv);
    __half* w1m = wh + 0 * (size_t)Hdim * Hdim;
    __half* w1v = wh + 1 * (size_t)Hdim * Hdim;
    __half* w2m = wh + 2 * (size_t)Hdim * Hdim;
    __half* w2v = wh + 3 * (size_t)Hdim * Hdim;

    const int SMEM_BYTES = PSTAGES * (BM + BN) * RSW * 4;  // 61440
    cudaFuncSetAttribute((const void*)gemm_fused<0, 0>,
                         cudaFuncAttributeMaxDynamicSharedMemorySize, SMEM_BYTES);
    cudaFuncSetAttribute((const void*)gemm_fused<1, 2>,
                         cudaFuncAttributeMaxDynamicSharedMemorySize, SMEM_BYTES);

    pack_all<<<1184, 256>>>(modal_a, (const float*)d_in[2], (const float*)d_in[6],
                            (const float*)d_in[4], (const float*)d_in[8], ah, wh);

    gemm_fused<0, 0><<<PGRID, 256, SMEM_BYTES>>>(ah, ah, w1m, w1v, b1m, b1v,
                                                 nullptr, nullptr, hm, hv);
    gemm_fused<1, 2><<<PGRID, 256, SMEM_BYTES>>>(hm, hv, w2m, w2v, b2m, b2v,
                                                 mu, iv, nullptr, nullptr);

    col_moments_s2<<<24, 256>>>();
    final_elem<<<1184, 256>>>(modal_b);
    final_reduce<<<1, 256>>>(out, 1184);
}

// round 9
// speedup vs baseline: 7.8343x; 1.0855x over previous
#include <cuda_runtime.h>
#include <cuda_fp16.h>
#include <cstdint>
#include <math.h>

#define Mdim 8192
#define Hdim 768
#define BM 128
#define BN 64
#define BK 32
#define RSW 20          // smem row stride in 32-bit words (40 halves)
#define NKT (Hdim / BK) // 24
#define PSTAGES 4       // cp.async pipeline depth (3 in flight)
#define NTILE_X (Hdim / BN)   // 12
#define NTILE_Y (Mdim / BM)   // 64
#define PGRID 444       // persistent grid: 3 CTAs/SM * 148

// ---------------- scratch (static device globals; no allocation) ----------------
__device__ __half g_ah[Mdim * Hdim];     // fp16 modal_a
__device__ __half g_wh[4][Hdim * Hdim];  // fp16 W1m, W1v, W2m, W2v
__device__ __half g_hm[Mdim * Hdim];     // fp16 tanh(layer1m)
__device__ __half g_hv[Mdim * Hdim];     // fp16 tanh(layer1v)
__device__ float g_mu[Mdim * Hdim];
__device__ float g_colpart[2][NTILE_Y][Hdim];
__device__ float g_colmean[Hdim];
__device__ float g_colsq[Hdim];
__device__ float g_part[PGRID * 2];

// ---------------------------- helpers -------------------------------------------
__device__ __forceinline__ uint32_t smem_u32(const void* p) {
    uint32_t a;
    asm("{ .reg .u64 t; cvta.to.shared.u64 t, %1; cvt.u32.u64 %0, t; }"
        : "=r"(a) : "l"(p));
    return a;
}
__device__ __forceinline__ float tanh_fast(float x) {
    float y;
    asm("tanh.approx.f32 %0, %1;" : "=f"(y) : "f"(x));
    return y;
}
#define LDSM_X4(r0, r1, r2, r3, addr) \
    asm volatile("ldmatrix.sync.aligned.m8n8.x4.shared.b16 {%0,%1,%2,%3}, [%4];" \
        : "=r"(r0), "=r"(r1), "=r"(r2), "=r"(r3) : "r"(addr))

// -------------------- pack: modal_a + all 4 weights, one launch ------------------
__global__ __launch_bounds__(256) void pack_all(
    const float* __restrict__ a,
    const float* __restrict__ w0, const float* __restrict__ w1,
    const float* __restrict__ w2, const float* __restrict__ w3,
    __half* __restrict__ ah, __half* __restrict__ wh) {
    const int na = Mdim * Hdim / 4;
    const int nw = Hdim * Hdim / 4;
    const int total = na + 4 * nw;
    for (int i = blockIdx.x * 256 + threadIdx.x; i < total; i += gridDim.x * 256) {
        const float* src;
        __half* dst;
        int idx;
        if (i < na) { src = a; dst = ah; idx = i; }
        else {
            int r = i - na;
            int wsel = r / nw;
            idx = r - wsel * nw;
            src = (wsel == 0) ? w0 : (wsel == 1) ? w1 : (wsel == 2) ? w2 : w3;
            dst = wh + (size_t)wsel * Hdim * Hdim;
        }
        float4 v = ((const float4*)src)[idx];
        __half2 h0 = __floats2half2_rn(v.x, v.y);
        __half2 h1 = __floats2half2_rn(v.z, v.w);
        *(uint2*)(dst + (size_t)idx * 4) =
            make_uint2(*(uint32_t*)&h0, *(uint32_t*)&h1);
    }
}

// -------------------- persistent fp16 GEMM, 3 epilogue kinds --------------------
// KIND 0: dual-branch layer 1; tiles 0..1535; z selects (A,W,bias,out); tanh->half
// KIND 1: layer-2 mu; tiles 0..767; fp32 store + column partials
// KIND 2: layer-2 iv + fused final loss epilogue (no iv store)
template <int KIND>
__global__ __launch_bounds__(256, 3) void gemm_pers(
    const __half* __restrict__ A0, const __half* __restrict__ A1,
    const __half* __restrict__ W0, const __half* __restrict__ W1,
    const float* __restrict__ bias0, const float* __restrict__ bias1,
    float* __restrict__ Pmu, __half* __restrict__ H0, __half* __restrict__ H1,
    const float* __restrict__ modal_b)
{
    extern __shared__ uint32_t sm[];
    const uint32_t sA = smem_u32(sm);
    const uint32_t sB = sA + PSTAGES * BM * RSW * 4;

    const int tid = threadIdx.x;
    const int wid = tid >> 5, lane = tid & 31;
    const int g = lane >> 2, tg = lane & 3;
    const int wm0 = (wid & 3) * 32;    // 4 warps along M
    const int wn0 = (wid >> 2) * 32;   // 2 warps along N

    const int lrow = tid >> 2;
    const int lc = tid & 3;
    const uint32_t dab = sA + (uint32_t)(lrow * RSW + lc * 4) * 4;
    const uint32_t dbb = sB + (uint32_t)(lrow * RSW + lc * 4) * 4;
    const uint32_t rowstep = 64 * RSW * 4;
    const uint32_t abufstep = BM * RSW * 4;
    const uint32_t bbufstep = BN * RSW * 4;

    const int mi = lane >> 3, mr = lane & 7;
    uint32_t aoff[2];
#pragma unroll
    for (int t = 0; t < 2; t++)
        aoff[t] = (uint32_t)(((wm0 + t * 16 + (mi & 1) * 8 + mr) * RSW + (mi >> 1) * 4) * 4);
    uint32_t boff[2];
#pragma unroll
    for (int jp = 0; jp < 2; jp++)
        boff[jp] = (uint32_t)(((wn0 + (jp * 2 + (mi >> 1)) * 8 + mr) * RSW + (mi & 1) * 4) * 4);

    float* sS = (float*)sm;          // reduction overlays
    float* sQ = sS + 256;

    const int ntiles = (KIND == 0) ? (NTILE_X * NTILE_Y * 2) : (NTILE_X * NTILE_Y);

    float accp = 0.0f, accd = 0.0f;  // KIND 2: per-thread loss partials

    for (int tile = blockIdx.x; tile < ntiles; tile += PGRID) {
        int z = 0, r = tile;
        if (KIND == 0 && tile >= NTILE_X * NTILE_Y) { z = 1; r = tile - NTILE_X * NTILE_Y; }
        const int by = r / NTILE_X;
        const int bx = r - by * NTILE_X;
        const int m0 = by * BM;
        const int n0 = bx * BN;

        const __half* A = z ? A1 : A0;
        const __half* Bw = z ? W1 : W0;
        const float* bias = z ? bias1 : bias0;

        const __half* agb = A + (size_t)(m0 + lrow) * Hdim + lc * 8;
        const __half* bgb = Bw + (size_t)(n0 + lrow) * Hdim + lc * 8;

        float c[2][4][4];
#pragma unroll
        for (int t = 0; t < 2; t++)
#pragma unroll
            for (int j = 0; j < 4; j++)
#pragma unroll
                for (int q = 0; q < 4; q++) c[t][j][q] = 0.0f;

#define PREFETCH(kt) do { \
    const __half* _ag = agb + (kt) * BK; \
    const __half* _bg = bgb + (kt) * BK; \
    uint32_t _da = dab + ((kt) % PSTAGES) * abufstep; \
    uint32_t _db = dbb + ((kt) % PSTAGES) * bbufstep; \
    asm volatile("cp.async.cg.shared.global [%0], [%1], 16;" \
        :: "r"(_da), "l"(_ag) : "memory"); \
    asm volatile("cp.async.cg.shared.global [%0], [%1], 16;" \
        :: "r"(_da + rowstep), "l"(_ag + (size_t)64 * Hdim) : "memory"); \
    if (lrow < BN) \
        asm volatile("cp.async.cg.shared.global [%0], [%1], 16;" \
            :: "r"(_db), "l"(_bg) : "memory"); \
    asm volatile("cp.async.commit_group;" ::: "memory"); \
} while (0)

        PREFETCH(0);
        PREFETCH(1);
        PREFETCH(2);

        for (int kt = 0; kt < NKT; kt++) {
            asm volatile("cp.async.wait_group 2;" ::: "memory");
            __syncthreads();

            if (kt + 3 < NKT) PREFETCH(kt + 3);
            else asm volatile("cp.async.commit_group;" ::: "memory");

            const uint32_t stA = sA + (kt % PSTAGES) * abufstep;
            const uint32_t stB = sB + (kt % PSTAGES) * bbufstep;
#pragma unroll
            for (int ks = 0; ks < 2; ks++) {
                const uint32_t ko = ks * 32;
                uint32_t a[2][4];
#pragma unroll
                for (int t = 0; t < 2; t++)
                    LDSM_X4(a[t][0], a[t][1], a[t][2], a[t][3], stA + aoff[t] + ko);
#pragma unroll
                for (int jp = 0; jp < 2; jp++) {
                    uint32_t b[4];
                    LDSM_X4(b[0], b[1], b[2], b[3], stB + boff[jp] + ko);
#pragma unroll
                    for (int t = 0; t < 2; t++) {
                        asm volatile(
                            "mma.sync.aligned.m16n8k16.row.col.f32.f16.f16.f32 "
                            "{%0,%1,%2,%3}, {%4,%5,%6,%7}, {%8,%9}, {%0,%1,%2,%3};"
                            : "+f"(c[t][jp * 2][0]), "+f"(c[t][jp * 2][1]),
                              "+f"(c[t][jp * 2][2]), "+f"(c[t][jp * 2][3])
                            : "r"(a[t][0]), "r"(a[t][1]), "r"(a[t][2]), "r"(a[t][3]),
                              "r"(b[0]), "r"(b[1]));
                        asm volatile(
                            "mma.sync.aligned.m16n8k16.row.col.f32.f16.f16.f32 "
                            "{%0,%1,%2,%3}, {%4,%5,%6,%7}, {%8,%9}, {%0,%1,%2,%3};"
                            : "+f"(c[t][jp * 2 + 1][0]), "+f"(c[t][jp * 2 + 1][1]),
                              "+f"(c[t][jp * 2 + 1][2]), "+f"(c[t][jp * 2 + 1][3])
                            : "r"(a[t][0]), "r"(a[t][1]), "r"(a[t][2]), "r"(a[t][3]),
                              "r"(b[2]), "r"(b[3]));
                    }
                }
            }
        }
#undef PREFETCH

        // -------- epilogue --------
        if (KIND == 1) __syncthreads();   // protect smem overlay vs last LDSM reads
#pragma unroll
        for (int j = 0; j < 4; j++) {
            const int ncol = n0 + wn0 + j * 8 + tg * 2;
            const float bv0 = bias[ncol];
            const float bv1 = bias[ncol + 1];
            float s0 = 0.f, s1 = 0.f, q0 = 0.f, q1 = 0.f;
            float cm0, cm1, cq0, cq1;
            if (KIND == 2) {
                float2 cm = *(const float2*)&g_colmean[ncol];
                float2 cq = *(const float2*)&g_colsq[ncol];
                cm0 = cm.x; cm1 = cm.y; cq0 = cq.x; cq1 = cq.y;
            }
#pragma unroll
            for (int t = 0; t < 2; t++) {
#pragma unroll
                for (int h = 0; h < 2; h++) {
                    const int row = m0 + wm0 + t * 16 + g + h * 8;
                    float v0 = c[t][j][h * 2 + 0] + bv0;
                    float v1 = c[t][j][h * 2 + 1] + bv1;
                    if (KIND == 0) {
                        __half2 hv = __floats2half2_rn(tanh_fast(v0), tanh_fast(v1));
                        __half* Ch = z ? H1 : H0;
                        *(__half2*)&Ch[(size_t)row * Hdim + ncol] = hv;
                    } else if (KIND == 1) {
                        *(float2*)&Pmu[(size_t)row * Hdim + ncol] = make_float2(v0, v1);
                        s0 += v0; q0 = fmaf(v0, v0, q0);
                        s1 += v1; q1 = fmaf(v1, v1, q1);
                    } else {
                        float iv0 = __expf(-tanhf(v0));
                        float iv1 = __expf(-tanhf(v1));
                        float2 mu2 = *(const float2*)&Pmu[(size_t)row * Hdim + ncol];
                        float2 mb2 = *(const float2*)&modal_b[(size_t)row * Hdim + ncol];
                        float d0 = mu2.x - mb2.x, d1 = mu2.y - mb2.y;
                        float pos0 = -d0 * d0 * 0.5f * iv0;
                        float pos1 = -d1 * d1 * 0.5f * iv1;
                        float pr0 = cq0 - 2.0f * mu2.x * cm0 + mu2.x * mu2.x;
                        float pr1 = cq1 - 2.0f * mu2.y * cm1 + mu2.y * mu2.y;
                        float neg0 = -pr0 * 0.5f * iv0;
                        float neg1 = -pr1 * 0.5f * iv1;
                        accp += pos0 + pos1;
                        accd += (pos0 - neg0) + (pos1 - neg1);
                    }
                }
            }
            if (KIND == 1) {
#pragma unroll
                for (int msk = 4; msk <= 16; msk <<= 1) {
                    s0 += __shfl_xor_sync(0xffffffffu, s0, msk);
                    q0 += __shfl_xor_sync(0xffffffffu, q0, msk);
                    s1 += __shfl_xor_sync(0xffffffffu, s1, msk);
                    q1 += __shfl_xor_sync(0xffffffffu, q1, msk);
                }
                if (lane < 4) {
                    const int cl = wn0 + j * 8 + tg * 2;
                    const int mw = wid & 3;
                    sS[mw * 64 + cl] = s0; sQ[mw * 64 + cl] = q0;
                    sS[mw * 64 + cl + 1] = s1; sQ[mw * 64 + cl + 1] = q1;
                }
            }
        }
        if (KIND == 1) {
            __syncthreads();
            if (tid < 64) {
                const int cl = tid;
                g_colpart[0][by][n0 + cl] =
                    sS[cl] + sS[64 + cl] + sS[128 + cl] + sS[192 + cl];
            } else if (tid < 128) {
                const int cl = tid - 64;
                g_colpart[1][by][n0 + cl] =
                    sQ[cl] + sQ[64 + cl] + sQ[128 + cl] + sQ[192 + cl];
            }
        }
        __syncthreads();   // end-of-tile: protect smem vs next tile's prefetch
    }

    if (KIND == 2) {
        // per-CTA deterministic reduction of loss partials
        sS[tid] = accp;
        sQ[tid] = accd;
        __syncthreads();
        for (int s = 128; s > 0; s >>= 1) {
            if (tid < s) { sS[tid] += sS[tid + s]; sQ[tid] += sQ[tid + s]; }
            __syncthreads();
        }
        if (tid == 0) {
            g_part[blockIdx.x * 2 + 0] = sS[0];
            g_part[blockIdx.x * 2 + 1] = sQ[0];
        }
    }
}

// ------------- column moments: parallel deterministic sum over 64 chunks ---------
__global__ __launch_bounds__(256) void col_moments_s2() {
    const int col = blockIdx.x * 32 + (threadIdx.x >> 3);
    const int sub = threadIdx.x & 7;
    float s = 0.0f, s2 = 0.0f;
#pragma unroll
    for (int k = 0; k < 8; k++) {
        int rc = sub * 8 + k;
        s += g_colpart[0][rc][col];
        s2 += g_colpart[1][rc][col];
    }
#pragma unroll
    for (int msk = 4; msk >= 1; msk >>= 1) {
        s += __shfl_xor_sync(0xffffffffu, s, msk);
        s2 += __shfl_xor_sync(0xffffffffu, s2, msk);
    }
    if (sub == 0) {
        const float invB = 1.0f / (float)Mdim;
        g_colmean[col] = s * invB;
        g_colsq[col] = s2 * invB;
    }
}

__global__ __launch_bounds__(256) void final_reduce(float* __restrict__ out, int nblocks) {
    __shared__ float shp[256];
    __shared__ float shd[256];
    const int tid = threadIdx.x;
    float sp = 0.0f, sd = 0.0f;
    for (int i = tid; i < nblocks; i += 256) {
        sp += g_part[i * 2 + 0];
        sd += g_part[i * 2 + 1];
    }
    shp[tid] = sp;
    shd[tid] = sd;
    __syncthreads();
    for (int s = 128; s > 0; s >>= 1) {
        if (tid < s) { shp[tid] += shp[tid + s]; shd[tid] += shd[tid + s]; }
        __syncthreads();
    }
    if (tid == 0) {
        const float invB = 1.0f / (float)Mdim;
        out[0] = shp[0] * invB;
        out[1] = shd[0] * invB;
    }
}

// --------------------------------- launcher --------------------------------------
extern "C" void kernel_launch(void* const* d_in, const int* in_sizes, int n_in,
                              void* d_out, int out_size) {
    const float* modal_a = (const float*)d_in[0];
    const float* modal_b = (const float*)d_in[1];
    const float* b1m = (const float*)d_in[3];
    const float* b2m = (const float*)d_in[5];
    const float* b1v = (const float*)d_in[7];
    const float* b2v = (const float*)d_in[9];
    float* out = (float*)d_out;

    __half *ah, *wh, *hm, *hv;
    float *mu;
    cudaGetSymbolAddress((void**)&ah, g_ah);
    cudaGetSymbolAddress((void**)&wh, g_wh);
    cudaGetSymbolAddress((void**)&hm, g_hm);
    cudaGetSymbolAddress((void**)&hv, g_hv);
    cudaGetSymbolAddress((void**)&mu, g_mu);
    __half* w1m = wh + 0 * (size_t)Hdim * Hdim;
    __half* w1v = wh + 1 * (size_t)Hdim * Hdim;
    __half* w2m = wh + 2 * (size_t)Hdim * Hdim;
    __half* w2v = wh + 3 * (size_t)Hdim * Hdim;

    const int SMEM_BYTES = PSTAGES * (BM + BN) * RSW * 4;  // 61440
    cudaFuncSetAttribute((const void*)gemm_pers<0>,
                         cudaFuncAttributeMaxDynamicSharedMemorySize, SMEM_BYTES);
    cudaFuncSetAttribute((const void*)gemm_pers<1>,
                         cudaFuncAttributeMaxDynamicSharedMemorySize, SMEM_BYTES);
    cudaFuncSetAttribute((const void*)gemm_pers<2>,
                         cudaFuncAttributeMaxDynamicSharedMemorySize, SMEM_BYTES);

    pack_all<<<1184, 256>>>(modal_a, (const float*)d_in[2], (const float*)d_in[6],
                            (const float*)d_in[4], (const float*)d_in[8], ah, wh);

    // layer 1: both branches (tanh -> half), 1536 tiles
    gemm_pers<0><<<PGRID, 256, SMEM_BYTES>>>(ah, ah, w1m, w1v, b1m, b1v,
                                             nullptr, hm, hv, nullptr);
    // layer 2 mu: fp32 store + column partials, 768 tiles
    gemm_pers<1><<<PGRID, 256, SMEM_BYTES>>>(hm, hm, w2m, w2m, b2m, b2m,
                                             mu, nullptr, nullptr, nullptr);
    col_moments_s2<<<24, 256>>>();
    // layer 2 iv + fused final loss epilogue, 768 tiles
    gemm_pers<2><<<PGRID, 256, SMEM_BYTES>>>(hv, hv, w2v, w2v, b2v, b2v,
                                             mu, nullptr, nullptr, modal_b);
    final_reduce<<<1, 256>>>(out, PGRID);
}

// round 10
// speedup vs baseline: 7.8936x; 1.0076x over previous
#include <cuda_runtime.h>
#include <cuda_fp16.h>
#include <cstdint>
#include <math.h>

#define Mdim 8192
#define Hdim 768
#define BM 128
#define BN 64
#define BK 32
#define RSW 20          // smem row stride in 32-bit words (40 halves)
#define NKT (Hdim / BK) // 24
#define PSTAGES 4       // cp.async pipeline depth (3 in flight)
#define NTILE_X (Hdim / BN)   // 12
#define NTILE_Y (Mdim / BM)   // 64
#define PGRID 444       // persistent grid: 3 CTAs/SM * 148 (L2 kernels)
#define PGRID2 296      // persistent grid: 2 CTAs/SM * 148 (L1 dual kernel)

// ---------------- scratch (static device globals; no allocation) ----------------
__device__ __half g_ah[Mdim * Hdim];     // fp16 modal_a
__device__ __half g_wh[4][Hdim * Hdim];  // fp16 W1m, W1v, W2m, W2v
__device__ __half g_hm[Mdim * Hdim];     // fp16 tanh(layer1m)
__device__ __half g_hv[Mdim * Hdim];     // fp16 tanh(layer1v)
__device__ float g_mu[Mdim * Hdim];
__device__ float g_colpart[2][NTILE_Y][Hdim];
__device__ float g_colmean[Hdim];
__device__ float g_colsq[Hdim];
__device__ float g_part[PGRID * 2];

// ---------------------------- helpers -------------------------------------------
__device__ __forceinline__ uint32_t smem_u32(const void* p) {
    uint32_t a;
    asm("{ .reg .u64 t; cvta.to.shared.u64 t, %1; cvt.u32.u64 %0, t; }"
        : "=r"(a) : "l"(p));
    return a;
}
__device__ __forceinline__ float tanh_fast(float x) {
    float y;
    asm("tanh.approx.f32 %0, %1;" : "=f"(y) : "f"(x));
    return y;
}
#define LDSM_X4(r0, r1, r2, r3, addr) \
    asm volatile("ldmatrix.sync.aligned.m8n8.x4.shared.b16 {%0,%1,%2,%3}, [%4];" \
        : "=r"(r0), "=r"(r1), "=r"(r2), "=r"(r3) : "r"(addr))
#define MMA16816(c0, c1, c2, c3, a0, a1, a2, a3, b0, b1) \
    asm volatile( \
        "mma.sync.aligned.m16n8k16.row.col.f32.f16.f16.f32 " \
        "{%0,%1,%2,%3}, {%4,%5,%6,%7}, {%8,%9}, {%0,%1,%2,%3};" \
        : "+f"(c0), "+f"(c1), "+f"(c2), "+f"(c3) \
        : "r"(a0), "r"(a1), "r"(a2), "r"(a3), "r"(b0), "r"(b1))

// -------------------- pack: modal_a + all 4 weights, one launch ------------------
__global__ __launch_bounds__(256) void pack_all(
    const float* __restrict__ a,
    const float* __restrict__ w0, const float* __restrict__ w1,
    const float* __restrict__ w2, const float* __restrict__ w3,
    __half* __restrict__ ah, __half* __restrict__ wh) {
    const int na = Mdim * Hdim / 4;
    const int nw = Hdim * Hdim / 4;
    const int total = na + 4 * nw;
    for (int i = blockIdx.x * 256 + threadIdx.x; i < total; i += gridDim.x * 256) {
        const float* src;
        __half* dst;
        int idx;
        if (i < na) { src = a; dst = ah; idx = i; }
        else {
            int r = i - na;
            int wsel = r / nw;
            idx = r - wsel * nw;
            src = (wsel == 0) ? w0 : (wsel == 1) ? w1 : (wsel == 2) ? w2 : w3;
            dst = wh + (size_t)wsel * Hdim * Hdim;
        }
        float4 v = ((const float4*)src)[idx];
        __half2 h0 = __floats2half2_rn(v.x, v.y);
        __half2 h1 = __floats2half2_rn(v.z, v.w);
        *(uint2*)(dst + (size_t)idx * 4) =
            make_uint2(*(uint32_t*)&h0, *(uint32_t*)&h1);
    }
}

// ---------------- layer-1 dual-branch GEMM: one A tile, two B tiles --------------
// Per tile: Hm[m0:,n0:] = tanh(A@W1m^T+b1m), Hv[...] = tanh(A@W1v^T+b1v)
__global__ __launch_bounds__(256, 2) void gemm_l1(
    const __half* __restrict__ A,
    const __half* __restrict__ W0, const __half* __restrict__ W1,
    const float* __restrict__ bias0, const float* __restrict__ bias1,
    __half* __restrict__ H0, __half* __restrict__ H1)
{
    extern __shared__ uint32_t sm[];
    const uint32_t sA = smem_u32(sm);
    const uint32_t sB0 = sA + PSTAGES * BM * RSW * 4;
    const uint32_t sB1 = sB0 + PSTAGES * BN * RSW * 4;

    const int tid = threadIdx.x;
    const int wid = tid >> 5, lane = tid & 31;
    const int g = lane >> 2, tg = lane & 3;
    const int wm0 = (wid & 3) * 32;    // 4 warps along M
    const int wn0 = (wid >> 2) * 32;   // 2 warps along N (per branch)

    const int lrow = tid >> 2;          // 0..63
    const int lc = tid & 3;
    const uint32_t dab = sA + (uint32_t)(lrow * RSW + lc * 4) * 4;
    const uint32_t db0 = sB0 + (uint32_t)(lrow * RSW + lc * 4) * 4;
    const uint32_t db1 = sB1 + (uint32_t)(lrow * RSW + lc * 4) * 4;
    const uint32_t rowstep = 64 * RSW * 4;
    const uint32_t abufstep = BM * RSW * 4;
    const uint32_t bbufstep = BN * RSW * 4;

    const int mi = lane >> 3, mr = lane & 7;
    uint32_t aoff[2];
#pragma unroll
    for (int t = 0; t < 2; t++)
        aoff[t] = (uint32_t)(((wm0 + t * 16 + (mi & 1) * 8 + mr) * RSW + (mi >> 1) * 4) * 4);
    uint32_t boff[2];
#pragma unroll
    for (int jp = 0; jp < 2; jp++)
        boff[jp] = (uint32_t)(((wn0 + (jp * 2 + (mi >> 1)) * 8 + mr) * RSW + (mi & 1) * 4) * 4);

    for (int tile = blockIdx.x; tile < NTILE_X * NTILE_Y; tile += PGRID2) {
        const int by = tile / NTILE_X;
        const int bx = tile - by * NTILE_X;
        const int m0 = by * BM;
        const int n0 = bx * BN;

        const __half* agb = A + (size_t)(m0 + lrow) * Hdim + lc * 8;
        const __half* b0gb = W0 + (size_t)(n0 + lrow) * Hdim + lc * 8;
        const __half* b1gb = W1 + (size_t)(n0 + lrow) * Hdim + lc * 8;

        float c[2][2][4][4];   // [branch][t][j][q]
#pragma unroll
        for (int br = 0; br < 2; br++)
#pragma unroll
            for (int t = 0; t < 2; t++)
#pragma unroll
                for (int j = 0; j < 4; j++)
#pragma unroll
                    for (int q = 0; q < 4; q++) c[br][t][j][q] = 0.0f;

#define PREFETCH(kt) do { \
    const __half* _ag = agb + (kt) * BK; \
    uint32_t _da = dab + ((kt) % PSTAGES) * abufstep; \
    asm volatile("cp.async.cg.shared.global [%0], [%1], 16;" \
        :: "r"(_da), "l"(_ag) : "memory"); \
    asm volatile("cp.async.cg.shared.global [%0], [%1], 16;" \
        :: "r"(_da + rowstep), "l"(_ag + (size_t)64 * Hdim) : "memory"); \
    asm volatile("cp.async.cg.shared.global [%0], [%1], 16;" \
        :: "r"(db0 + ((kt) % PSTAGES) * bbufstep), "l"(b0gb + (kt) * BK) : "memory"); \
    asm volatile("cp.async.cg.shared.global [%0], [%1], 16;" \
        :: "r"(db1 + ((kt) % PSTAGES) * bbufstep), "l"(b1gb + (kt) * BK) : "memory"); \
    asm volatile("cp.async.commit_group;" ::: "memory"); \
} while (0)

        PREFETCH(0);
        PREFETCH(1);
        PREFETCH(2);

        for (int kt = 0; kt < NKT; kt++) {
            asm volatile("cp.async.wait_group 2;" ::: "memory");
            __syncthreads();

            if (kt + 3 < NKT) PREFETCH(kt + 3);
            else asm volatile("cp.async.commit_group;" ::: "memory");

            const uint32_t stA = sA + (kt % PSTAGES) * abufstep;
            const uint32_t stB0 = sB0 + (kt % PSTAGES) * bbufstep;
            const uint32_t stB1 = sB1 + (kt % PSTAGES) * bbufstep;
#pragma unroll
            for (int ks = 0; ks < 2; ks++) {
                const uint32_t ko = ks * 32;
                uint32_t a[2][4];
#pragma unroll
                for (int t = 0; t < 2; t++)
                    LDSM_X4(a[t][0], a[t][1], a[t][2], a[t][3], stA + aoff[t] + ko);
#pragma unroll
                for (int jp = 0; jp < 2; jp++) {
                    uint32_t b[4];
                    LDSM_X4(b[0], b[1], b[2], b[3], stB0 + boff[jp] + ko);
#pragma unroll
                    for (int t = 0; t < 2; t++) {
                        MMA16816(c[0][t][jp*2][0], c[0][t][jp*2][1], c[0][t][jp*2][2], c[0][t][jp*2][3],
                                 a[t][0], a[t][1], a[t][2], a[t][3], b[0], b[1]);
                        MMA16816(c[0][t][jp*2+1][0], c[0][t][jp*2+1][1], c[0][t][jp*2+1][2], c[0][t][jp*2+1][3],
                                 a[t][0], a[t][1], a[t][2], a[t][3], b[2], b[3]);
                    }
                }
#pragma unroll
                for (int jp = 0; jp < 2; jp++) {
                    uint32_t b[4];
                    LDSM_X4(b[0], b[1], b[2], b[3], stB1 + boff[jp] + ko);
#pragma unroll
                    for (int t = 0; t < 2; t++) {
                        MMA16816(c[1][t][jp*2][0], c[1][t][jp*2][1], c[1][t][jp*2][2], c[1][t][jp*2][3],
                                 a[t][0], a[t][1], a[t][2], a[t][3], b[0], b[1]);
                        MMA16816(c[1][t][jp*2+1][0], c[1][t][jp*2+1][1], c[1][t][jp*2+1][2], c[1][t][jp*2+1][3],
                                 a[t][0], a[t][1], a[t][2], a[t][3], b[2], b[3]);
                    }
                }
            }
        }
#undef PREFETCH

        // -------- epilogue: both branches, tanh -> half --------
#pragma unroll
        for (int br = 0; br < 2; br++) {
            const float* bias = br ? bias1 : bias0;
            __half* Ch = br ? H1 : H0;
#pragma unroll
            for (int j = 0; j < 4; j++) {
                const int ncol = n0 + wn0 + j * 8 + tg * 2;
                const float bv0 = bias[ncol];
                const float bv1 = bias[ncol + 1];
#pragma unroll
                for (int t = 0; t < 2; t++) {
#pragma unroll
                    for (int h = 0; h < 2; h++) {
                        const int row = m0 + wm0 + t * 16 + g + h * 8;
                        float v0 = c[br][t][j][h * 2 + 0] + bv0;
                        float v1 = c[br][t][j][h * 2 + 1] + bv1;
                        __half2 hv = __floats2half2_rn(tanh_fast(v0), tanh_fast(v1));
                        *(__half2*)&Ch[(size_t)row * Hdim + ncol] = hv;
                    }
                }
            }
        }
        __syncthreads();   // protect smem vs next tile's prefetch
    }
}

// -------------------- persistent fp16 GEMM, layer-2 epilogues --------------------
// KIND 1: layer-2 mu; fp32 store + column partials
// KIND 2: layer-2 iv + fused final loss epilogue (no iv store)
template <int KIND>
__global__ __launch_bounds__(256, 3) void gemm_pers(
    const __half* __restrict__ A0,
    const __half* __restrict__ W0,
    const float* __restrict__ bias0,
    float* __restrict__ Pmu,
    const float* __restrict__ modal_b)
{
    extern __shared__ uint32_t sm[];
    const uint32_t sA = smem_u32(sm);
    const uint32_t sB = sA + PSTAGES * BM * RSW * 4;

    const int tid = threadIdx.x;
    const int wid = tid >> 5, lane = tid & 31;
    const int g = lane >> 2, tg = lane & 3;
    const int wm0 = (wid & 3) * 32;
    const int wn0 = (wid >> 2) * 32;

    const int lrow = tid >> 2;
    const int lc = tid & 3;
    const uint32_t dab = sA + (uint32_t)(lrow * RSW + lc * 4) * 4;
    const uint32_t dbb = sB + (uint32_t)(lrow * RSW + lc * 4) * 4;
    const uint32_t rowstep = 64 * RSW * 4;
    const uint32_t abufstep = BM * RSW * 4;
    const uint32_t bbufstep = BN * RSW * 4;

    const int mi = lane >> 3, mr = lane & 7;
    uint32_t aoff[2];
#pragma unroll
    for (int t = 0; t < 2; t++)
        aoff[t] = (uint32_t)(((wm0 + t * 16 + (mi & 1) * 8 + mr) * RSW + (mi >> 1) * 4) * 4);
    uint32_t boff[2];
#pragma unroll
    for (int jp = 0; jp < 2; jp++)
        boff[jp] = (uint32_t)(((wn0 + (jp * 2 + (mi >> 1)) * 8 + mr) * RSW + (mi & 1) * 4) * 4);

    float* sS = (float*)sm;
    float* sQ = sS + 256;

    float accp = 0.0f, accd = 0.0f;

    for (int tile = blockIdx.x; tile < NTILE_X * NTILE_Y; tile += PGRID) {
        const int by = tile / NTILE_X;
        const int bx = tile - by * NTILE_X;
        const int m0 = by * BM;
        const int n0 = bx * BN;

        const __half* agb = A0 + (size_t)(m0 + lrow) * Hdim + lc * 8;
        const __half* bgb = W0 + (size_t)(n0 + lrow) * Hdim + lc * 8;

        float c[2][4][4];
#pragma unroll
        for (int t = 0; t < 2; t++)
#pragma unroll
            for (int j = 0; j < 4; j++)
#pragma unroll
                for (int q = 0; q < 4; q++) c[t][j][q] = 0.0f;

#define PREFETCH(kt) do { \
    const __half* _ag = agb + (kt) * BK; \
    const __half* _bg = bgb + (kt) * BK; \
    uint32_t _da = dab + ((kt) % PSTAGES) * abufstep; \
    uint32_t _db = dbb + ((kt) % PSTAGES) * bbufstep; \
    asm volatile("cp.async.cg.shared.global [%0], [%1], 16;" \
        :: "r"(_da), "l"(_ag) : "memory"); \
    asm volatile("cp.async.cg.shared.global [%0], [%1], 16;" \
        :: "r"(_da + rowstep), "l"(_ag + (size_t)64 * Hdim) : "memory"); \
    if (lrow < BN) \
        asm volatile("cp.async.cg.shared.global [%0], [%1], 16;" \
            :: "r"(_db), "l"(_bg) : "memory"); \
    asm volatile("cp.async.commit_group;" ::: "memory"); \
} while (0)

        PREFETCH(0);
        PREFETCH(1);
        PREFETCH(2);

        for (int kt = 0; kt < NKT; kt++) {
            asm volatile("cp.async.wait_group 2;" ::: "memory");
            __syncthreads();

            if (kt + 3 < NKT) PREFETCH(kt + 3);
            else asm volatile("cp.async.commit_group;" ::: "memory");

            const uint32_t stA = sA + (kt % PSTAGES) * abufstep;
            const uint32_t stB = sB + (kt % PSTAGES) * bbufstep;
#pragma unroll
            for (int ks = 0; ks < 2; ks++) {
                const uint32_t ko = ks * 32;
                uint32_t a[2][4];
#pragma unroll
                for (int t = 0; t < 2; t++)
                    LDSM_X4(a[t][0], a[t][1], a[t][2], a[t][3], stA + aoff[t] + ko);
#pragma unroll
                for (int jp = 0; jp < 2; jp++) {
                    uint32_t b[4];
                    LDSM_X4(b[0], b[1], b[2], b[3], stB + boff[jp] + ko);
#pragma unroll
                    for (int t = 0; t < 2; t++) {
                        MMA16816(c[t][jp*2][0], c[t][jp*2][1], c[t][jp*2][2], c[t][jp*2][3],
                                 a[t][0], a[t][1], a[t][2], a[t][3], b[0], b[1]);
                        MMA16816(c[t][jp*2+1][0], c[t][jp*2+1][1], c[t][jp*2+1][2], c[t][jp*2+1][3],
                                 a[t][0], a[t][1], a[t][2], a[t][3], b[2], b[3]);
                    }
                }
            }
        }
#undef PREFETCH

        // -------- epilogue --------
        if (KIND == 1) __syncthreads();   // protect smem overlay vs last LDSM reads
#pragma unroll
        for (int j = 0; j < 4; j++) {
            const int ncol = n0 + wn0 + j * 8 + tg * 2;
            const float bv0 = bias0[ncol];
            const float bv1 = bias0[ncol + 1];
            float s0 = 0.f, s1 = 0.f, q0 = 0.f, q1 = 0.f;
            float cm0, cm1, cq0, cq1;
            if (KIND == 2) {
                float2 cm = *(const float2*)&g_colmean[ncol];
                float2 cq = *(const float2*)&g_colsq[ncol];
                cm0 = cm.x; cm1 = cm.y; cq0 = cq.x; cq1 = cq.y;
            }
#pragma unroll
            for (int t = 0; t < 2; t++) {
#pragma unroll
                for (int h = 0; h < 2; h++) {
                    const int row = m0 + wm0 + t * 16 + g + h * 8;
                    float v0 = c[t][j][h * 2 + 0] + bv0;
                    float v1 = c[t][j][h * 2 + 1] + bv1;
                    if (KIND == 1) {
                        *(float2*)&Pmu[(size_t)row * Hdim + ncol] = make_float2(v0, v1);
                        s0 += v0; q0 = fmaf(v0, v0, q0);
                        s1 += v1; q1 = fmaf(v1, v1, q1);
                    } else {
                        float iv0 = __expf(-tanhf(v0));
                        float iv1 = __expf(-tanhf(v1));
                        float2 mu2 = *(const float2*)&Pmu[(size_t)row * Hdim + ncol];
                        float2 mb2 = *(const float2*)&modal_b[(size_t)row * Hdim + ncol];
                        float d0 = mu2.x - mb2.x, d1 = mu2.y - mb2.y;
                        float pos0 = -d0 * d0 * 0.5f * iv0;
                        float pos1 = -d1 * d1 * 0.5f * iv1;
                        float pr0 = cq0 - 2.0f * mu2.x * cm0 + mu2.x * mu2.x;
                        float pr1 = cq1 - 2.0f * mu2.y * cm1 + mu2.y * mu2.y;
                        float neg0 = -pr0 * 0.5f * iv0;
                        float neg1 = -pr1 * 0.5f * iv1;
                        accp += pos0 + pos1;
                        accd += (pos0 - neg0) + (pos1 - neg1);
                    }
                }
            }
            if (KIND == 1) {
#pragma unroll
                for (int msk = 4; msk <= 16; msk <<= 1) {
                    s0 += __shfl_xor_sync(0xffffffffu, s0, msk);
                    q0 += __shfl_xor_sync(0xffffffffu, q0, msk);
                    s1 += __shfl_xor_sync(0xffffffffu, s1, msk);
                    q1 += __shfl_xor_sync(0xffffffffu, q1, msk);
                }
                if (lane < 4) {
                    const int cl = wn0 + j * 8 + tg * 2;
                    const int mw = wid & 3;
                    sS[mw * 64 + cl] = s0; sQ[mw * 64 + cl] = q0;
                    sS[mw * 64 + cl + 1] = s1; sQ[mw * 64 + cl + 1] = q1;
                }
            }
        }
        if (KIND == 1) {
            __syncthreads();
            if (tid < 64) {
                const int cl = tid;
                g_colpart[0][by][n0 + cl] =
                    sS[cl] + sS[64 + cl] + sS[128 + cl] + sS[192 + cl];
            } else if (tid < 128) {
                const int cl = tid - 64;
                g_colpart[1][by][n0 + cl] =
                    sQ[cl] + sQ[64 + cl] + sQ[128 + cl] + sQ[192 + cl];
            }
        }
        __syncthreads();
    }

    if (KIND == 2) {
        sS[tid] = accp;
        sQ[tid] = accd;
        __syncthreads();
        for (int s = 128; s > 0; s >>= 1) {
            if (tid < s) { sS[tid] += sS[tid + s]; sQ[tid] += sQ[tid + s]; }
            __syncthreads();
        }
        if (tid == 0) {
            g_part[blockIdx.x * 2 + 0] = sS[0];
            g_part[blockIdx.x * 2 + 1] = sQ[0];
        }
    }
}

// ------------- column moments: parallel deterministic sum over 64 chunks ---------
__global__ __launch_bounds__(256) void col_moments_s2() {
    const int col = blockIdx.x * 32 + (threadIdx.x >> 3);
    const int sub = threadIdx.x & 7;
    float s = 0.0f, s2 = 0.0f;
#pragma unroll
    for (int k = 0; k < 8; k++) {
        int rc = sub * 8 + k;
        s += g_colpart[0][rc][col];
        s2 += g_colpart[1][rc][col];
    }
#pragma unroll
    for (int msk = 4; msk >= 1; msk >>= 1) {
        s += __shfl_xor_sync(0xffffffffu, s, msk);
        s2 += __shfl_xor_sync(0xffffffffu, s2, msk);
    }
    if (sub == 0) {
        const float invB = 1.0f / (float)Mdim;
        g_colmean[col] = s * invB;
        g_colsq[col] = s2 * invB;
    }
}

__global__ __launch_bounds__(256) void final_reduce(float* __restrict__ out, int nblocks) {
    __shared__ float shp[256];
    __shared__ float shd[256];
    const int tid = threadIdx.x;
    float sp = 0.0f, sd = 0.0f;
    for (int i = tid; i < nblocks; i += 256) {
        sp += g_part[i * 2 + 0];
        sd += g_part[i * 2 + 1];
    }
    shp[tid] = sp;
    shd[tid] = sd;
    __syncthreads();
    for (int s = 128; s > 0; s >>= 1) {
        if (tid < s) { shp[tid] += shp[tid + s]; shd[tid] += shd[tid + s]; }
        __syncthreads();
    }
    if (tid == 0) {
        const float invB = 1.0f / (float)Mdim;
        out[0] = shp[0] * invB;
        out[1] = shd[0] * invB;
    }
}

// --------------------------------- launcher --------------------------------------
extern "C" void kernel_launch(void* const* d_in, const int* in_sizes, int n_in,
                              void* d_out, int out_size) {
    const float* modal_a = (const float*)d_in[0];
    const float* modal_b = (const float*)d_in[1];
    const float* b1m = (const float*)d_in[3];
    const float* b2m = (const float*)d_in[5];
    const float* b1v = (const float*)d_in[7];
    const float* b2v = (const float*)d_in[9];
    float* out = (float*)d_out;

    __half *ah, *wh, *hm, *hv;
    float *mu;
    cudaGetSymbolAddress((void**)&ah, g_ah);
    cudaGetSymbolAddress((void**)&wh, g_wh);
    cudaGetSymbolAddress((void**)&hm, g_hm);
    cudaGetSymbolAddress((void**)&hv, g_hv);
    cudaGetSymbolAddress((void**)&mu, g_mu);
    __half* w1m = wh + 0 * (size_t)Hdim * Hdim;
    __half* w1v = wh + 1 * (size_t)Hdim * Hdim;
    __half* w2m = wh + 2 * (size_t)Hdim * Hdim;
    __half* w2v = wh + 3 * (size_t)Hdim * Hdim;

    const int SMEM_L1 = PSTAGES * (BM + 2 * BN) * RSW * 4;  // 81920
    const int SMEM_L2 = PSTAGES * (BM + BN) * RSW * 4;      // 61440
    cudaFuncSetAttribute((const void*)gemm_l1,
                         cudaFuncAttributeMaxDynamicSharedMemorySize, SMEM_L1);
    cudaFuncSetAttribute((const void*)gemm_pers<1>,
                         cudaFuncAttributeMaxDynamicSharedMemorySize, SMEM_L2);
    cudaFuncSetAttribute((const void*)gemm_pers<2>,
                         cudaFuncAttributeMaxDynamicSharedMemorySize, SMEM_L2);

    pack_all<<<1184, 256>>>(modal_a, (const float*)d_in[2], (const float*)d_in[6],
                            (const float*)d_in[4], (const float*)d_in[8], ah, wh);

    // layer 1: both branches in one tile (shared A), 768 tiles
    gemm_l1<<<PGRID2, 256, SMEM_L1>>>(ah, w1m, w1v, b1m, b1v, hm, hv);
    // layer 2 mu: fp32 store + column partials
    gemm_pers<1><<<PGRID, 256, SMEM_L2>>>(hm, w2m, b2m, mu, nullptr);
    col_moments_s2<<<24, 256>>>();
    // layer 2 iv + fused final loss epilogue
    gemm_pers<2><<<PGRID, 256, SMEM_L2>>>(hv, w2v, b2v, mu, modal_b);
    final_reduce<<<1, 256>>>(out, PGRID);
}

// round 11
// speedup vs baseline: 8.3104x; 1.0528x over previous
#include <cuda_runtime.h>
#include <cuda_fp16.h>
#include <cstdint>
#include <math.h>

#define Mdim 8192
#define Hdim 768
#define BM 128
#define BN 64
#define BK 32
#define RSW 20          // smem row stride in 32-bit words (40 halves)
#define NKT (Hdim / BK) // 24
#define PSTAGES 4       // cp.async pipeline depth (3 in flight)
#define NTILE_X (Hdim / BN)   // 12
#define NTILE_Y (Mdim / BM)   // 64
#define NTILES (NTILE_X * NTILE_Y)  // 768
#define PGRID 444       // persistent grid: 3 CTAs/SM * 148 (L2 kernels)
#define PGRID2 296      // persistent grid: 2 CTAs/SM * 148 (L1 dual kernel)

// ---------------- scratch (static device globals; no allocation) ----------------
__device__ __half g_ah[Mdim * Hdim];     // fp16 modal_a
__device__ __half g_wh[4][Hdim * Hdim];  // fp16 W1m, W1v, W2m, W2v
__device__ __half g_hm[Mdim * Hdim];     // fp16 tanh(layer1m)
__device__ __half g_hv[Mdim * Hdim];     // fp16 tanh(layer1v)
__device__ __half g_muh[Mdim * Hdim];    // fp16 mu
__device__ float g_colpart[2][NTILE_Y][Hdim];
__device__ float g_colmean[Hdim];
__device__ float g_colsq[Hdim];
__device__ float g_part[NTILES * 2];     // per-tile loss partials
__device__ int g_ctr[4];                 // work-stealing counters

// ---------------------------- helpers -------------------------------------------
__device__ __forceinline__ uint32_t smem_u32(const void* p) {
    uint32_t a;
    asm("{ .reg .u64 t; cvta.to.shared.u64 t, %1; cvt.u32.u64 %0, t; }"
        : "=r"(a) : "l"(p));
    return a;
}
__device__ __forceinline__ float tanh_fast(float x) {
    float y;
    asm("tanh.approx.f32 %0, %1;" : "=f"(y) : "f"(x));
    return y;
}
#define LDSM_X4(r0, r1, r2, r3, addr) \
    asm volatile("ldmatrix.sync.aligned.m8n8.x4.shared.b16 {%0,%1,%2,%3}, [%4];" \
        : "=r"(r0), "=r"(r1), "=r"(r2), "=r"(r3) : "r"(addr))
#define MMA16816(c0, c1, c2, c3, a0, a1, a2, a3, b0, b1) \
    asm volatile( \
        "mma.sync.aligned.m16n8k16.row.col.f32.f16.f16.f32 " \
        "{%0,%1,%2,%3}, {%4,%5,%6,%7}, {%8,%9}, {%0,%1,%2,%3};" \
        : "+f"(c0), "+f"(c1), "+f"(c2), "+f"(c3) \
        : "r"(a0), "r"(a1), "r"(a2), "r"(a3), "r"(b0), "r"(b1))

// -------------------- pack: modal_a + all 4 weights, one launch ------------------
__global__ __launch_bounds__(256) void pack_all(
    const float* __restrict__ a,
    const float* __restrict__ w0, const float* __restrict__ w1,
    const float* __restrict__ w2, const float* __restrict__ w3,
    __half* __restrict__ ah, __half* __restrict__ wh) {
    if (blockIdx.x == 0 && threadIdx.x < 4) g_ctr[threadIdx.x] = 0;  // reset schedulers
    const int na = Mdim * Hdim / 4;
    const int nw = Hdim * Hdim / 4;
    const int total = na + 4 * nw;
    for (int i = blockIdx.x * 256 + threadIdx.x; i < total; i += gridDim.x * 256) {
        const float* src;
        __half* dst;
        int idx;
        if (i < na) { src = a; dst = ah; idx = i; }
        else {
            int r = i - na;
            int wsel = r / nw;
            idx = r - wsel * nw;
            src = (wsel == 0) ? w0 : (wsel == 1) ? w1 : (wsel == 2) ? w2 : w3;
            dst = wh + (size_t)wsel * Hdim * Hdim;
        }
        float4 v = ((const float4*)src)[idx];
        __half2 h0 = __floats2half2_rn(v.x, v.y);
        __half2 h1 = __floats2half2_rn(v.z, v.w);
        *(uint2*)(dst + (size_t)idx * 4) =
            make_uint2(*(uint32_t*)&h0, *(uint32_t*)&h1);
    }
}

// ---------------- layer-1 dual-branch GEMM: one A tile, two B tiles --------------
__global__ __launch_bounds__(256, 2) void gemm_l1(
    const __half* __restrict__ A,
    const __half* __restrict__ W0, const __half* __restrict__ W1,
    const float* __restrict__ bias0, const float* __restrict__ bias1,
    __half* __restrict__ H0, __half* __restrict__ H1)
{
    extern __shared__ uint32_t sm[];
    __shared__ int s_tile;
    const uint32_t sA = smem_u32(sm);
    const uint32_t sB0 = sA + PSTAGES * BM * RSW * 4;
    const uint32_t sB1 = sB0 + PSTAGES * BN * RSW * 4;

    const int tid = threadIdx.x;
    const int wid = tid >> 5, lane = tid & 31;
    const int g = lane >> 2, tg = lane & 3;
    const int wm0 = (wid & 3) * 32;
    const int wn0 = (wid >> 2) * 32;

    const int lrow = tid >> 2;
    const int lc = tid & 3;
    const uint32_t dab = sA + (uint32_t)(lrow * RSW + lc * 4) * 4;
    const uint32_t db0 = sB0 + (uint32_t)(lrow * RSW + lc * 4) * 4;
    const uint32_t db1 = sB1 + (uint32_t)(lrow * RSW + lc * 4) * 4;
    const uint32_t rowstep = 64 * RSW * 4;
    const uint32_t abufstep = BM * RSW * 4;
    const uint32_t bbufstep = BN * RSW * 4;

    const int mi = lane >> 3, mr = lane & 7;
    uint32_t aoff[2];
#pragma unroll
    for (int t = 0; t < 2; t++)
        aoff[t] = (uint32_t)(((wm0 + t * 16 + (mi & 1) * 8 + mr) * RSW + (mi >> 1) * 4) * 4);
    uint32_t boff[2];
#pragma unroll
    for (int jp = 0; jp < 2; jp++)
        boff[jp] = (uint32_t)(((wn0 + (jp * 2 + (mi >> 1)) * 8 + mr) * RSW + (mi & 1) * 4) * 4);

    while (true) {
        if (tid == 0) s_tile = atomicAdd(&g_ctr[0], 1);
        __syncthreads();
        const int tile = s_tile;
        if (tile >= NTILES) break;
        __syncthreads();   // all threads read s_tile before next rewrite / smem reuse

        const int by = tile / NTILE_X;
        const int bx = tile - by * NTILE_X;
        const int m0 = by * BM;
        const int n0 = bx * BN;

        const __half* agb = A + (size_t)(m0 + lrow) * Hdim + lc * 8;
        const __half* b0gb = W0 + (size_t)(n0 + lrow) * Hdim + lc * 8;
        const __half* b1gb = W1 + (size_t)(n0 + lrow) * Hdim + lc * 8;

        float c[2][2][4][4];
#pragma unroll
        for (int br = 0; br < 2; br++)
#pragma unroll
            for (int t = 0; t < 2; t++)
#pragma unroll
                for (int j = 0; j < 4; j++)
#pragma unroll
                    for (int q = 0; q < 4; q++) c[br][t][j][q] = 0.0f;

#define PREFETCH(kt) do { \
    const __half* _ag = agb + (kt) * BK; \
    uint32_t _da = dab + ((kt) % PSTAGES) * abufstep; \
    asm volatile("cp.async.cg.shared.global [%0], [%1], 16;" \
        :: "r"(_da), "l"(_ag) : "memory"); \
    asm volatile("cp.async.cg.shared.global [%0], [%1], 16;" \
        :: "r"(_da + rowstep), "l"(_ag + (size_t)64 * Hdim) : "memory"); \
    asm volatile("cp.async.cg.shared.global [%0], [%1], 16;" \
        :: "r"(db0 + ((kt) % PSTAGES) * bbufstep), "l"(b0gb + (kt) * BK) : "memory"); \
    asm volatile("cp.async.cg.shared.global [%0], [%1], 16;" \
        :: "r"(db1 + ((kt) % PSTAGES) * bbufstep), "l"(b1gb + (kt) * BK) : "memory"); \
    asm volatile("cp.async.commit_group;" ::: "memory"); \
} while (0)

        PREFETCH(0);
        PREFETCH(1);
        PREFETCH(2);

        for (int kt = 0; kt < NKT; kt++) {
            asm volatile("cp.async.wait_group 2;" ::: "memory");
            __syncthreads();

            if (kt + 3 < NKT) PREFETCH(kt + 3);
            else asm volatile("cp.async.commit_group;" ::: "memory");

            const uint32_t stA = sA + (kt % PSTAGES) * abufstep;
            const uint32_t stB0 = sB0 + (kt % PSTAGES) * bbufstep;
            const uint32_t stB1 = sB1 + (kt % PSTAGES) * bbufstep;
#pragma unroll
            for (int ks = 0; ks < 2; ks++) {
                const uint32_t ko = ks * 32;
                uint32_t a[2][4];
#pragma unroll
                for (int t = 0; t < 2; t++)
                    LDSM_X4(a[t][0], a[t][1], a[t][2], a[t][3], stA + aoff[t] + ko);
#pragma unroll
                for (int jp = 0; jp < 2; jp++) {
                    uint32_t b[4];
                    LDSM_X4(b[0], b[1], b[2], b[3], stB0 + boff[jp] + ko);
#pragma unroll
                    for (int t = 0; t < 2; t++) {
                        MMA16816(c[0][t][jp*2][0], c[0][t][jp*2][1], c[0][t][jp*2][2], c[0][t][jp*2][3],
                                 a[t][0], a[t][1], a[t][2], a[t][3], b[0], b[1]);
                        MMA16816(c[0][t][jp*2+1][0], c[0][t][jp*2+1][1], c[0][t][jp*2+1][2], c[0][t][jp*2+1][3],
                                 a[t][0], a[t][1], a[t][2], a[t][3], b[2], b[3]);
                    }
                }
#pragma unroll
                for (int jp = 0; jp < 2; jp++) {
                    uint32_t b[4];
                    LDSM_X4(b[0], b[1], b[2], b[3], stB1 + boff[jp] + ko);
#pragma unroll
                    for (int t = 0; t < 2; t++) {
                        MMA16816(c[1][t][jp*2][0], c[1][t][jp*2][1], c[1][t][jp*2][2], c[1][t][jp*2][3],
                                 a[t][0], a[t][1], a[t][2], a[t][3], b[0], b[1]);
                        MMA16816(c[1][t][jp*2+1][0], c[1][t][jp*2+1][1], c[1][t][jp*2+1][2], c[1][t][jp*2+1][3],
                                 a[t][0], a[t][1], a[t][2], a[t][3], b[2], b[3]);
                    }
                }
            }
        }
#undef PREFETCH

        // -------- epilogue: both branches, tanh -> half --------
#pragma unroll
        for (int br = 0; br < 2; br++) {
            const float* bias = br ? bias1 : bias0;
            __half* Ch = br ? H1 : H0;
#pragma unroll
            for (int j = 0; j < 4; j++) {
                const int ncol = n0 + wn0 + j * 8 + tg * 2;
                const float bv0 = bias[ncol];
                const float bv1 = bias[ncol + 1];
#pragma unroll
                for (int t = 0; t < 2; t++) {
#pragma unroll
                    for (int h = 0; h < 2; h++) {
                        const int row = m0 + wm0 + t * 16 + g + h * 8;
                        float v0 = c[br][t][j][h * 2 + 0] + bv0;
                        float v1 = c[br][t][j][h * 2 + 1] + bv1;
                        __half2 hv = __floats2half2_rn(tanh_fast(v0), tanh_fast(v1));
                        *(__half2*)&Ch[(size_t)row * Hdim + ncol] = hv;
                    }
                }
            }
        }
        __syncthreads();   // smem + s_tile safe before next iteration
    }
}

// -------------------- persistent fp16 GEMM, layer-2 epilogues --------------------
// KIND 1: layer-2 mu; fp16 store + column partials (counter 1)
// KIND 2: layer-2 iv + fused final loss epilogue, per-tile partials (counter 2)
template <int KIND>
__global__ __launch_bounds__(256, 3) void gemm_pers(
    const __half* __restrict__ A0,
    const __half* __restrict__ W0,
    const float* __restrict__ bias0,
    __half* __restrict__ Pmu,
    const float* __restrict__ modal_b)
{
    extern __shared__ uint32_t sm[];
    __shared__ int s_tile;
    const uint32_t sA = smem_u32(sm);
    const uint32_t sB = sA + PSTAGES * BM * RSW * 4;

    const int tid = threadIdx.x;
    const int wid = tid >> 5, lane = tid & 31;
    const int g = lane >> 2, tg = lane & 3;
    const int wm0 = (wid & 3) * 32;
    const int wn0 = (wid >> 2) * 32;

    const int lrow = tid >> 2;
    const int lc = tid & 3;
    const uint32_t dab = sA + (uint32_t)(lrow * RSW + lc * 4) * 4;
    const uint32_t dbb = sB + (uint32_t)(lrow * RSW + lc * 4) * 4;
    const uint32_t rowstep = 64 * RSW * 4;
    const uint32_t abufstep = BM * RSW * 4;
    const uint32_t bbufstep = BN * RSW * 4;

    const int mi = lane >> 3, mr = lane & 7;
    uint32_t aoff[2];
#pragma unroll
    for (int t = 0; t < 2; t++)
        aoff[t] = (uint32_t)(((wm0 + t * 16 + (mi & 1) * 8 + mr) * RSW + (mi >> 1) * 4) * 4);
    uint32_t boff[2];
#pragma unroll
    for (int jp = 0; jp < 2; jp++)
        boff[jp] = (uint32_t)(((wn0 + (jp * 2 + (mi >> 1)) * 8 + mr) * RSW + (mi & 1) * 4) * 4);

    float* sS = (float*)sm;
    float* sQ = sS + 256;

    while (true) {
        if (tid == 0) s_tile = atomicAdd(&g_ctr[KIND], 1);
        __syncthreads();
        const int tile = s_tile;
        if (tile >= NTILES) break;
        __syncthreads();

        const int by = tile / NTILE_X;
        const int bx = tile - by * NTILE_X;
        const int m0 = by * BM;
        const int n0 = bx * BN;

        const __half* agb = A0 + (size_t)(m0 + lrow) * Hdim + lc * 8;
        const __half* bgb = W0 + (size_t)(n0 + lrow) * Hdim + lc * 8;

        float c[2][4][4];
#pragma unroll
        for (int t = 0; t < 2; t++)
#pragma unroll
            for (int j = 0; j < 4; j++)
#pragma unroll
                for (int q = 0; q < 4; q++) c[t][j][q] = 0.0f;

#define PREFETCH(kt) do { \
    const __half* _ag = agb + (kt) * BK; \
    const __half* _bg = bgb + (kt) * BK; \
    uint32_t _da = dab + ((kt) % PSTAGES) * abufstep; \
    uint32_t _db = dbb + ((kt) % PSTAGES) * bbufstep; \
    asm volatile("cp.async.cg.shared.global [%0], [%1], 16;" \
        :: "r"(_da), "l"(_ag) : "memory"); \
    asm volatile("cp.async.cg.shared.global [%0], [%1], 16;" \
        :: "r"(_da + rowstep), "l"(_ag + (size_t)64 * Hdim) : "memory"); \
    if (lrow < BN) \
        asm volatile("cp.async.cg.shared.global [%0], [%1], 16;" \
            :: "r"(_db), "l"(_bg) : "memory"); \
    asm volatile("cp.async.commit_group;" ::: "memory"); \
} while (0)

        PREFETCH(0);
        PREFETCH(1);
        PREFETCH(2);

        for (int kt = 0; kt < NKT; kt++) {
            asm volatile("cp.async.wait_group 2;" ::: "memory");
            __syncthreads();

            if (kt + 3 < NKT) PREFETCH(kt + 3);
            else asm volatile("cp.async.commit_group;" ::: "memory");

            const uint32_t stA = sA + (kt % PSTAGES) * abufstep;
            const uint32_t stB = sB + (kt % PSTAGES) * bbufstep;
#pragma unroll
            for (int ks = 0; ks < 2; ks++) {
                const uint32_t ko = ks * 32;
                uint32_t a[2][4];
#pragma unroll
                for (int t = 0; t < 2; t++)
                    LDSM_X4(a[t][0], a[t][1], a[t][2], a[t][3], stA + aoff[t] + ko);
#pragma unroll
                for (int jp = 0; jp < 2; jp++) {
                    uint32_t b[4];
                    LDSM_X4(b[0], b[1], b[2], b[3], stB + boff[jp] + ko);
#pragma unroll
                    for (int t = 0; t < 2; t++) {
                        MMA16816(c[t][jp*2][0], c[t][jp*2][1], c[t][jp*2][2], c[t][jp*2][3],
                                 a[t][0], a[t][1], a[t][2], a[t][3], b[0], b[1]);
                        MMA16816(c[t][jp*2+1][0], c[t][jp*2+1][1], c[t][jp*2+1][2], c[t][jp*2+1][3],
                                 a[t][0], a[t][1], a[t][2], a[t][3], b[2], b[3]);
                    }
                }
            }
        }
#undef PREFETCH

        // -------- epilogue --------
        float accp = 0.0f, accd = 0.0f;   // KIND 2: per-tile partials
        __syncthreads();                  // smem overlay safe (all warps past k-loop)
#pragma unroll
        for (int j = 0; j < 4; j++) {
            const int ncol = n0 + wn0 + j * 8 + tg * 2;
            const float bv0 = bias0[ncol];
            const float bv1 = bias0[ncol + 1];
            float s0 = 0.f, s1 = 0.f, q0 = 0.f, q1 = 0.f;
            float cm0, cm1, cq0, cq1;
            if (KIND == 2) {
                float2 cm = *(const float2*)&g_colmean[ncol];
                float2 cq = *(const float2*)&g_colsq[ncol];
                cm0 = cm.x; cm1 = cm.y; cq0 = cq.x; cq1 = cq.y;
            }
#pragma unroll
            for (int t = 0; t < 2; t++) {
#pragma unroll
                for (int h = 0; h < 2; h++) {
                    const int row = m0 + wm0 + t * 16 + g + h * 8;
                    float v0 = c[t][j][h * 2 + 0] + bv0;
                    float v1 = c[t][j][h * 2 + 1] + bv1;
                    if (KIND == 1) {
                        __half2 mh = __floats2half2_rn(v0, v1);
                        *(__half2*)&Pmu[(size_t)row * Hdim + ncol] = mh;
                        s0 += v0; q0 = fmaf(v0, v0, q0);
                        s1 += v1; q1 = fmaf(v1, v1, q1);
                    } else {
                        float iv0 = __expf(-tanhf(v0));
                        float iv1 = __expf(-tanhf(v1));
                        __half2 mh = *(const __half2*)&Pmu[(size_t)row * Hdim + ncol];
                        float2 mu2 = __half22float2(mh);
                        float2 mb2 = *(const float2*)&modal_b[(size_t)row * Hdim + ncol];
                        float d0 = mu2.x - mb2.x, d1 = mu2.y - mb2.y;
                        float pos0 = -d0 * d0 * 0.5f * iv0;
                        float pos1 = -d1 * d1 * 0.5f * iv1;
                        float pr0 = cq0 - 2.0f * mu2.x * cm0 + mu2.x * mu2.x;
                        float pr1 = cq1 - 2.0f * mu2.y * cm1 + mu2.y * mu2.y;
                        float neg0 = -pr0 * 0.5f * iv0;
                        float neg1 = -pr1 * 0.5f * iv1;
                        accp += pos0 + pos1;
                        accd += (pos0 - neg0) + (pos1 - neg1);
                    }
                }
            }
            if (KIND == 1) {
#pragma unroll
                for (int msk = 4; msk <= 16; msk <<= 1) {
                    s0 += __shfl_xor_sync(0xffffffffu, s0, msk);
                    q0 += __shfl_xor_sync(0xffffffffu, q0, msk);
                    s1 += __shfl_xor_sync(0xffffffffu, s1, msk);
                    q1 += __shfl_xor_sync(0xffffffffu, q1, msk);
                }
                if (lane < 4) {
                    const int cl = wn0 + j * 8 + tg * 2;
                    const int mw = wid & 3;
                    sS[mw * 64 + cl] = s0; sQ[mw * 64 + cl] = q0;
                    sS[mw * 64 + cl + 1] = s1; sQ[mw * 64 + cl + 1] = q1;
                }
            }
        }
        if (KIND == 1) {
            __syncthreads();
            if (tid < 64) {
                const int cl = tid;
                g_colpart[0][by][n0 + cl] =
                    sS[cl] + sS[64 + cl] + sS[128 + cl] + sS[192 + cl];
            } else if (tid < 128) {
                const int cl = tid - 64;
                g_colpart[1][by][n0 + cl] =
                    sQ[cl] + sQ[64 + cl] + sQ[128 + cl] + sQ[192 + cl];
            }
        } else {
            // per-tile deterministic loss reduction
            sS[tid] = accp;
            sQ[tid] = accd;
            __syncthreads();
            for (int s = 128; s > 0; s >>= 1) {
                if (tid < s) { sS[tid] += sS[tid + s]; sQ[tid] += sQ[tid + s]; }
                __syncthreads();
            }
            if (tid == 0) {
                g_part[tile * 2 + 0] = sS[0];
                g_part[tile * 2 + 1] = sQ[0];
            }
        }
        __syncthreads();
    }
}

// ------------- column moments: parallel deterministic sum over 64 chunks ---------
__global__ __launch_bounds__(256) void col_moments_s2() {
    const int col = blockIdx.x * 32 + (threadIdx.x >> 3);
    const int sub = threadIdx.x & 7;
    float s = 0.0f, s2 = 0.0f;
#pragma unroll
    for (int k = 0; k < 8; k++) {
        int rc = sub * 8 + k;
        s += g_colpart[0][rc][col];
        s2 += g_colpart[1][rc][col];
    }
#pragma unroll
    for (int msk = 4; msk >= 1; msk >>= 1) {
        s += __shfl_xor_sync(0xffffffffu, s, msk);
        s2 += __shfl_xor_sync(0xffffffffu, s2, msk);
    }
    if (sub == 0) {
        const float invB = 1.0f / (float)Mdim;
        g_colmean[col] = s * invB;
        g_colsq[col] = s2 * invB;
    }
}

__global__ __launch_bounds__(256) void final_reduce(float* __restrict__ out, int nblocks) {
    __shared__ float shp[256];
    __shared__ float shd[256];
    const int tid = threadIdx.x;
    float sp = 0.0f, sd = 0.0f;
    for (int i = tid; i < nblocks; i += 256) {
        sp += g_part[i * 2 + 0];
        sd += g_part[i * 2 + 1];
    }
    shp[tid] = sp;
    shd[tid] = sd;
    __syncthreads();
    for (int s = 128; s > 0; s >>= 1) {
        if (tid < s) { shp[tid] += shp[tid + s]; shd[tid] += shd[tid + s]; }
        __syncthreads();
    }
    if (tid == 0) {
        const float invB = 1.0f / (float)Mdim;
        out[0] = shp[0] * invB;
        out[1] = shd[0] * invB;
    }
}

// --------------------------------- launcher --------------------------------------
extern "C" void kernel_launch(void* const* d_in, const int* in_sizes, int n_in,
                              void* d_out, int out_size) {
    const float* modal_a = (const float*)d_in[0];
    const float* modal_b = (const float*)d_in[1];
    const float* b1m = (const float*)d_in[3];
    const float* b2m = (const float*)d_in[5];
    const float* b1v = (const float*)d_in[7];
    const float* b2v = (const float*)d_in[9];
    float* out = (float*)d_out;

    __half *ah, *wh, *hm, *hv, *muh;
    cudaGetSymbolAddress((void**)&ah, g_ah);
    cudaGetSymbolAddress((void**)&wh, g_wh);
    cudaGetSymbolAddress((void**)&hm, g_hm);
    cudaGetSymbolAddress((void**)&hv, g_hv);
    cudaGetSymbolAddress((void**)&muh, g_muh);
    __half* w1m = wh + 0 * (size_t)Hdim * Hdim;
    __half* w1v = wh + 1 * (size_t)Hdim * Hdim;
    __half* w2m = wh + 2 * (size_t)Hdim * Hdim;
    __half* w2v = wh + 3 * (size_t)Hdim * Hdim;

    const int SMEM_L1 = PSTAGES * (BM + 2 * BN) * RSW * 4;  // 81920
    const int SMEM_L2 = PSTAGES * (BM + BN) * RSW * 4;      // 61440
    cudaFuncSetAttribute((const void*)gemm_l1,
                         cudaFuncAttributeMaxDynamicSharedMemorySize, SMEM_L1);
    cudaFuncSetAttribute((const void*)gemm_pers<1>,
                         cudaFuncAttributeMaxDynamicSharedMemorySize, SMEM_L2);
    cudaFuncSetAttribute((const void*)gemm_pers<2>,
                         cudaFuncAttributeMaxDynamicSharedMemorySize, SMEM_L2);

    pack_all<<<1184, 256>>>(modal_a, (const float*)d_in[2], (const float*)d_in[6],
                            (const float*)d_in[4], (const float*)d_in[8], ah, wh);

    // layer 1: both branches in one tile (shared A), dynamic scheduling
    gemm_l1<<<PGRID2, 256, SMEM_L1>>>(ah, w1m, w1v, b1m, b1v, hm, hv);
    // layer 2 mu: fp16 store + column partials
    gemm_pers<1><<<PGRID, 256, SMEM_L2>>>(hm, w2m, b2m, muh, nullptr);
    col_moments_s2<<<24, 256>>>();
    // layer 2 iv + fused final loss epilogue (per-tile partials)
    gemm_pers<2><<<PGRID, 256, SMEM_L2>>>(hv, w2v, b2v, muh, modal_b);
    final_reduce<<<1, 256>>>(out, NTILES);
}